// round 4
// baseline (speedup 1.0000x reference)
#include <cuda_runtime.h>
#include <math.h>

#define NFFT 5000
#define NFULL 10000
#define NROWS (256*20)          // 5120 FFT rows
#define FFT_THREADS 256
#define FFT_SMEM (2*NFFT*8)     // 80000 bytes: two float2 buffers

#define PAD_A 108               // 108 % 32 = 12 -> conflict-free LDS.128 lane pattern
#define PAD_W 104
#define GEMM_ROWS 128
#define GEMM_SMEM ((GEMM_ROWS*PAD_A + 32*PAD_W)*4)   // 68608 bytes
#define FINAL_SMEM (6*3200*4 + 256)                   // W2 + reduction pad

// ---------------- scratch (no allocations allowed) ----------------
__device__ float2 d_wtab[NFFT];                 // exp(-2*pi*i*k/5000)
__device__ float  d_xl[(size_t)256*20*10000];   // log|FFT(x)|, layout [b][c][j]
__device__ float  d_x2[(size_t)256*32*100];     // relu(conv1), layout [b][o][s]

// ---------------- twiddle table ----------------
__global__ void twiddle_kernel() {
    int k = blockIdx.x * blockDim.x + threadIdx.x;
    if (k < NFFT) {
        double ang = -2.0 * 3.14159265358979323846 * (double)k / (double)NFFT;
        d_wtab[k] = make_float2((float)cos(ang), (float)sin(ang));
    }
}

__device__ __forceinline__ float2 cmulf(float2 a, float2 b) {
    return make_float2(a.x*b.x - a.y*b.y, a.x*b.y + a.y*b.x);
}

// ---------------- radix-5 Stockham stage (float2 smem) ----------------
template<int NS>
__device__ __forceinline__ void radix5_stage(const float2* __restrict__ a,
                                             float2* __restrict__ b, int tid) {
    const int STEP = NFFT / (NS * 5);
    #pragma unroll 1
    for (int j = tid; j < NFFT/5; j += FFT_THREADS) {
        const int m = j % NS;
        const int t = m * STEP;
        float2 x0 = a[j];
        float2 x1 = cmulf(a[j+1000], d_wtab[t]);
        float2 x2 = cmulf(a[j+2000], d_wtab[2*t]);
        float2 x3 = cmulf(a[j+3000], d_wtab[3*t]);
        float2 x4 = cmulf(a[j+4000], d_wtab[4*t]);
        float t1r = x1.x + x4.x, t1i = x1.y + x4.y;
        float t2r = x2.x + x3.x, t2i = x2.y + x3.y;
        float t3r = x1.x - x4.x, t3i = x1.y - x4.y;
        float t4r = x2.x - x3.x, t4i = x2.y - x3.y;
        const float c1 =  0.309016994374947424f;   // cos(2pi/5)
        const float c2 = -0.809016994374947424f;   // cos(4pi/5)
        const float s1 =  0.951056516295153572f;   // sin(2pi/5)
        const float s2 =  0.587785252292473129f;   // sin(4pi/5)
        float y0r = x0.x + t1r + t2r, y0i = x0.y + t1i + t2i;
        float par = x0.x + c1*t1r + c2*t2r, pai = x0.y + c1*t1i + c2*t2i;
        float pbr = s1*t3r + s2*t4r,        pbi = s1*t3i + s2*t4i;
        float pcr = x0.x + c2*t1r + c1*t2r, pci = x0.y + c2*t1i + c1*t2i;
        float pdr = s2*t3r - s1*t4r,        pdi = s2*t3i - s1*t4i;
        const int d = (j / NS) * (NS*5) + m;
        b[d]        = make_float2(y0r,       y0i);
        b[d +   NS] = make_float2(par + pbi, pai - pbr);   // X1 = P - iQ
        b[d + 2*NS] = make_float2(pcr + pdi, pci - pdr);
        b[d + 3*NS] = make_float2(pcr - pdi, pci + pdr);
        b[d + 4*NS] = make_float2(par - pbi, pai + pbr);
    }
}

// ---------------- radix-8 Stockham stage: NS=625, R=8, STEP=1 ----------------
__device__ __forceinline__ void radix8_stage(const float2* __restrict__ a,
                                             float2* __restrict__ b, int tid) {
    #pragma unroll 1
    for (int j = tid; j < 625; j += FFT_THREADS) {
        float2 y0 = a[j];
        float2 y1 = cmulf(a[j+ 625], d_wtab[j]);
        float2 y2 = cmulf(a[j+1250], d_wtab[2*j]);
        float2 y3 = cmulf(a[j+1875], d_wtab[3*j]);
        float2 y4 = cmulf(a[j+2500], d_wtab[4*j]);
        float2 y5 = cmulf(a[j+3125], d_wtab[5*j]);
        float2 y6 = cmulf(a[j+3750], d_wtab[6*j]);
        float2 y7 = cmulf(a[j+4375], d_wtab[7*j]);
        // E = FFT4(y0,y2,y4,y6)
        float t0r=y0.x+y4.x, t0i=y0.y+y4.y;
        float t1r=y0.x-y4.x, t1i=y0.y-y4.y;
        float t2r=y2.x+y6.x, t2i=y2.y+y6.y;
        float t3r=y2.x-y6.x, t3i=y2.y-y6.y;
        float E0r=t0r+t2r, E0i=t0i+t2i;
        float E1r=t1r+t3i, E1i=t1i-t3r;
        float E2r=t0r-t2r, E2i=t0i-t2i;
        float E3r=t1r-t3i, E3i=t1i+t3r;
        // O = FFT4(y1,y3,y5,y7)
        float u0r=y1.x+y5.x, u0i=y1.y+y5.y;
        float u1r=y1.x-y5.x, u1i=y1.y-y5.y;
        float u2r=y3.x+y7.x, u2i=y3.y+y7.y;
        float u3r=y3.x-y7.x, u3i=y3.y-y7.y;
        float O0r=u0r+u2r, O0i=u0i+u2i;
        float O1r=u1r+u3i, O1i=u1i-u3r;
        float O2r=u0r-u2r, O2i=u0i-u2i;
        float O3r=u1r-u3i, O3i=u1i+u3r;
        const float C = 0.70710678118654752440f;   // sqrt(2)/2
        float a1r = C*(O1r+O1i), a1i = C*(O1i-O1r);   // W8^1 * O1
        float a2r = O2i,         a2i = -O2r;          // W8^2 * O2 = -i*O2
        float a3r = C*(O3i-O3r), a3i = -C*(O3r+O3i);  // W8^3 * O3
        b[j]      = make_float2(E0r+O0r, E0i+O0i);
        b[j+ 625] = make_float2(E1r+a1r, E1i+a1i);
        b[j+1250] = make_float2(E2r+a2r, E2i+a2i);
        b[j+1875] = make_float2(E3r+a3r, E3i+a3i);
        b[j+2500] = make_float2(E0r-O0r, E0i-O0i);
        b[j+3125] = make_float2(E1r-a1r, E1i-a1i);
        b[j+3750] = make_float2(E2r-a2r, E2i-a2i);
        b[j+4375] = make_float2(E3r-a3r, E3i-a3i);
    }
}

// ---------------- Pass 1: real FFT (length 10000 via 5000-pack) + log|.| ----------------
__global__ __launch_bounds__(FFT_THREADS, 2)
void fft_logabs_kernel(const float* __restrict__ x) {
    extern __shared__ float2 sm2[];
    float2* buf0 = sm2;
    float2* buf1 = sm2 + NFFT;
    const int tid = threadIdx.x;
    const size_t row = blockIdx.x;

    // pack: z[n] = x[2n] + i*x[2n+1]
    const float2* xin = (const float2*)(x + row * NFULL);
    #pragma unroll 1
    for (int n = tid; n < NFFT; n += FFT_THREADS) buf0[n] = xin[n];
    __syncthreads();

    radix5_stage<1>  (buf0, buf1, tid); __syncthreads();
    radix5_stage<5>  (buf1, buf0, tid); __syncthreads();
    radix5_stage<25> (buf0, buf1, tid); __syncthreads();
    radix5_stage<125>(buf1, buf0, tid); __syncthreads();
    radix8_stage     (buf0, buf1, tid); __syncthreads();
    // Z[k] in buf1

    float* outp = d_xl + row * NFULL;
    #pragma unroll 1
    for (int k = tid; k <= 2500; k += FFT_THREADS) {
        const int km = (k == 0) ? 0 : (NFFT - k);
        float2 zk  = buf1[k];
        float2 zkm = buf1[km];
        float Er = 0.5f*(zk.x + zkm.x), Ei = 0.5f*(zk.y - zkm.y);
        float Or = 0.5f*(zk.y + zkm.y), Oi = 0.5f*(zkm.x - zk.x);
        float s, c;
        sincospif(-(float)k * (1.0f/5000.0f), &s, &c);
        float tr = c*Or - s*Oi;
        float ti = c*Oi + s*Or;
        float pr = Er + tr, pi = Ei + ti;   // X[k]
        float mr = Er - tr, mi = Ei - ti;   // X[5000+k]; |X[5000+k]| == |X[5000-k]|
        float l1 = 0.5f * logf(pr*pr + pi*pi);
        float l2 = 0.5f * logf(mr*mr + mi*mi);
        outp[k]        = l1;
        outp[5000 - k] = l2;
        if (k > 0) {
            outp[10000 - k] = l1;
            outp[5000 + k]  = l2;
        }
    }
}

// ---------------- Pass 2: per-segment GEMM ----------------
// x2[b,o,s] = relu( sum_{c,k} xl[b,c,s*100+k] * W1[s,o,c,k] + b1[s,o] )
// Grid 200 = (segment) x (batch half). Block: 128 threads, tile 4b x 8o per thread.
__global__ __launch_bounds__(128, 3)
void seg_gemm_kernel(const float* __restrict__ W1, const float* __restrict__ b1) {
    extern __shared__ float sm[];
    float* Asm = sm;                        // [128][PAD_A]
    float* Wsm = sm + GEMM_ROWS * PAD_A;    // [32][PAD_W]
    const int s    = blockIdx.x >> 1;
    const int b0   = (blockIdx.x & 1) * GEMM_ROWS;
    const int tid  = threadIdx.x;
    const int lane = tid & 31;              // b lane (local b = lane + 32*i, i<4)
    const int o0   = (tid >> 5) * 8;        // 8 o per thread

    float acc[4][8];
    #pragma unroll
    for (int i = 0; i < 4; i++)
        #pragma unroll
        for (int j = 0; j < 8; j++) acc[i][j] = 0.0f;

    for (int c = 0; c < 20; c++) {
        // A tile: 128 b-rows x 100 floats (float4, coalesced)
        #pragma unroll 1
        for (int q = tid; q < GEMM_ROWS*25; q += 128) {
            int b  = q / 25;
            int kq = q % 25;
            float4 v = *(const float4*)(d_xl + ((size_t)(b0 + b)*20 + c)*10000 + s*100 + kq*4);
            *(float4*)(Asm + b*PAD_A + kq*4) = v;
        }
        // W tile: 32 o-rows x 100 floats
        #pragma unroll 1
        for (int q = tid; q < 800; q += 128) {
            int o  = q / 25;
            int kq = q % 25;
            float4 v = *(const float4*)(W1 + (((size_t)s*32 + o)*20 + c)*100 + kq*4);
            *(float4*)(Wsm + o*PAD_W + kq*4) = v;
        }
        __syncthreads();

        #pragma unroll 1
        for (int k = 0; k < 100; k += 4) {
            float4 av[4];
            #pragma unroll
            for (int i = 0; i < 4; i++)
                av[i] = *(const float4*)(Asm + (lane + 32*i)*PAD_A + k);
            float4 wv[8];
            #pragma unroll
            for (int j = 0; j < 8; j++)                       // warp-uniform: LDS broadcast
                wv[j] = *(const float4*)(Wsm + (o0 + j)*PAD_W + k);
            #pragma unroll
            for (int i = 0; i < 4; i++)
                #pragma unroll
                for (int j = 0; j < 8; j++) {
                    acc[i][j] += av[i].x * wv[j].x;
                    acc[i][j] += av[i].y * wv[j].y;
                    acc[i][j] += av[i].z * wv[j].z;
                    acc[i][j] += av[i].w * wv[j].w;
                }
        }
        __syncthreads();
    }

    #pragma unroll
    for (int i = 0; i < 4; i++) {
        int b = b0 + lane + 32*i;
        #pragma unroll
        for (int j = 0; j < 8; j++) {
            int o = o0 + j;
            float v = acc[i][j] + b1[s*32 + o];
            d_x2[((size_t)b*32 + o)*100 + s] = fmaxf(v, 0.0f);
        }
    }
}

// ---------------- Pass 3: out[b,j] = relu(sum_i x2[b][i] * W2[j][i] + b2[j]) ----------------
// Grid 64 blocks x 256 threads; each block handles 4 batch rows, W2 staged in smem.
__global__ __launch_bounds__(256)
void final_kernel(const float* __restrict__ W2, const float* __restrict__ b2,
                  float* __restrict__ out) {
    extern __shared__ float fsm[];
    float* W2s = fsm;                 // [6][3200]
    float* red = fsm + 6*3200;        // [8][6]
    const int tid = threadIdx.x;

    #pragma unroll 1
    for (int i = tid; i < 6*3200; i += 256) W2s[i] = W2[i];
    __syncthreads();

    for (int bi = 0; bi < 4; bi++) {
        const int b = blockIdx.x * 4 + bi;
        const float* xb = d_x2 + (size_t)b * 3200;
        float acc[6] = {0.f, 0.f, 0.f, 0.f, 0.f, 0.f};
        #pragma unroll 1
        for (int i = tid; i < 3200; i += 256) {
            float v = xb[i];
            #pragma unroll
            for (int j = 0; j < 6; j++) acc[j] += v * W2s[j*3200 + i];
        }
        #pragma unroll
        for (int off = 16; off > 0; off >>= 1)
            #pragma unroll
            for (int j = 0; j < 6; j++)
                acc[j] += __shfl_xor_sync(0xFFFFFFFFu, acc[j], off);
        if ((tid & 31) == 0)
            #pragma unroll
            for (int j = 0; j < 6; j++) red[(tid >> 5)*6 + j] = acc[j];
        __syncthreads();
        if (tid < 6) {
            float t = b2[tid];
            #pragma unroll
            for (int w = 0; w < 8; w++) t += red[w*6 + tid];
            out[b*6 + tid] = fmaxf(t, 0.0f);
        }
        __syncthreads();
    }
}

// ---------------- launch ----------------
extern "C" void kernel_launch(void* const* d_in, const int* in_sizes, int n_in,
                              void* d_out, int out_size) {
    (void)in_sizes; (void)n_in; (void)out_size;
    const float* x  = (const float*)d_in[0];
    const float* W1 = (const float*)d_in[1];
    const float* b1 = (const float*)d_in[2];
    const float* W2 = (const float*)d_in[3];
    const float* b2 = (const float*)d_in[4];
    float* out = (float*)d_out;

    cudaFuncSetAttribute(fft_logabs_kernel, cudaFuncAttributeMaxDynamicSharedMemorySize, FFT_SMEM);
    cudaFuncSetAttribute(seg_gemm_kernel,   cudaFuncAttributeMaxDynamicSharedMemorySize, GEMM_SMEM);
    cudaFuncSetAttribute(final_kernel,      cudaFuncAttributeMaxDynamicSharedMemorySize, FINAL_SMEM);

    twiddle_kernel<<<20, 256>>>();
    fft_logabs_kernel<<<NROWS, FFT_THREADS, FFT_SMEM>>>(x);
    seg_gemm_kernel<<<200, 128, GEMM_SMEM>>>(W1, b1);
    final_kernel<<<64, 256, FINAL_SMEM>>>(W2, b2, out);
}

// round 7
// speedup vs baseline: 1.2592x; 1.2592x over previous
#include <cuda_runtime.h>
#include <math.h>

// FFTConv pipeline, round 7 submission.
// Pass 1: length-10000 real FFT per (b,c) row via packed length-5000 complex FFT
//         (Stockham, 4x radix-5 + 1x radix-8), then log|X[k]| for all 10000 bins.
// Pass 2: 100 per-segment GEMMs (M=256 batch, N=32 out-ch, K=2000) + bias + relu.
// Pass 3: final contraction (256x6x3200) + bias + relu.

#define NFFT 5000
#define NFULL 10000
#define NROWS (256*20)          // 5120 FFT rows
#define FFT_THREADS 256
#define FFT_SMEM (2*NFFT*8)     // 80000 bytes: two float2 ping-pong buffers

#define PAD_A 108               // 108 % 32 = 12 -> conflict-free LDS.128 lane pattern
#define PAD_W 104
#define GEMM_ROWS 128           // batch rows per block (2 blocks per segment)
#define GEMM_SMEM ((GEMM_ROWS*PAD_A + 32*PAD_W)*4)   // 68608 bytes

// ---------------- device scratch (no runtime allocations permitted) ----------------
__device__ float2 g_wtab[NFULL];                // w[k] = exp(-2*pi*i*k/10000)
__device__ float  g_xl[(size_t)256*20*10000];   // log|FFT(x)|, layout [b][c][j]
__device__ float  g_x2[(size_t)256*32*100];     // relu(conv1), layout [b][o][s]

// ---------------- twiddle table fill ----------------
__global__ void fill_twiddles_kernel() {
    int k = blockIdx.x * blockDim.x + threadIdx.x;
    if (k < NFULL) {
        double ang = -2.0 * 3.14159265358979323846 * (double)k / (double)NFULL;
        g_wtab[k] = make_float2((float)cos(ang), (float)sin(ang));
    }
}

__device__ __forceinline__ float2 cxmul(float2 a, float2 b) {
    return make_float2(a.x*b.x - a.y*b.y, a.x*b.y + a.y*b.x);
}

// ---------------- radix-5 Stockham stage (float2 smem) ----------------
// Length-5000 twiddle exp(-2pi*i*t/5000) = g_wtab[2*t] (10000-entry table).
template<int NS>
__device__ __forceinline__ void stage_r5(const float2* __restrict__ a,
                                         float2* __restrict__ b, int tid) {
    const int STEP = NFFT / (NS * 5);
    for (int j = tid; j < NFFT/5; j += FFT_THREADS) {
        const int m = j % NS;
        const int t = 2 * m * STEP;
        float2 x0 = a[j];
        float2 x1 = cxmul(a[j+1000], g_wtab[t]);
        float2 x2 = cxmul(a[j+2000], g_wtab[2*t]);
        float2 x3 = cxmul(a[j+3000], g_wtab[3*t]);
        float2 x4 = cxmul(a[j+4000], g_wtab[4*t]);
        float t1r = x1.x + x4.x, t1i = x1.y + x4.y;
        float t2r = x2.x + x3.x, t2i = x2.y + x3.y;
        float t3r = x1.x - x4.x, t3i = x1.y - x4.y;
        float t4r = x2.x - x3.x, t4i = x2.y - x3.y;
        const float c1 =  0.309016994374947424f;   // cos(2pi/5)
        const float c2 = -0.809016994374947424f;   // cos(4pi/5)
        const float s1 =  0.951056516295153572f;   // sin(2pi/5)
        const float s2 =  0.587785252292473129f;   // sin(4pi/5)
        float y0r = x0.x + t1r + t2r, y0i = x0.y + t1i + t2i;
        float par = x0.x + c1*t1r + c2*t2r, pai = x0.y + c1*t1i + c2*t2i;
        float pbr = s1*t3r + s2*t4r,        pbi = s1*t3i + s2*t4i;
        float pcr = x0.x + c2*t1r + c1*t2r, pci = x0.y + c2*t1i + c1*t2i;
        float pdr = s2*t3r - s1*t4r,        pdi = s2*t3i - s1*t4i;
        const int d = (j / NS) * (NS*5) + m;
        b[d]        = make_float2(y0r,       y0i);
        b[d +   NS] = make_float2(par + pbi, pai - pbr);   // X1 = P - iQ
        b[d + 2*NS] = make_float2(pcr + pdi, pci - pdr);
        b[d + 3*NS] = make_float2(pcr - pdi, pci + pdr);
        b[d + 4*NS] = make_float2(par - pbi, pai + pbr);
    }
}

// ---------------- radix-8 Stockham stage: NS=625, R=8 ----------------
__device__ __forceinline__ void stage_r8(const float2* __restrict__ a,
                                         float2* __restrict__ b, int tid) {
    for (int j = tid; j < 625; j += FFT_THREADS) {
        const int t = 2 * j;             // exp(-2pi*i*j/5000) in the 10000-table
        float2 y0 = a[j];
        float2 y1 = cxmul(a[j+ 625], g_wtab[t]);
        float2 y2 = cxmul(a[j+1250], g_wtab[2*t]);
        float2 y3 = cxmul(a[j+1875], g_wtab[3*t]);
        float2 y4 = cxmul(a[j+2500], g_wtab[4*t]);
        float2 y5 = cxmul(a[j+3125], g_wtab[5*t]);
        float2 y6 = cxmul(a[j+3750], g_wtab[6*t]);
        float2 y7 = cxmul(a[j+4375], g_wtab[7*t]);
        // E = FFT4(y0,y2,y4,y6)
        float t0r=y0.x+y4.x, t0i=y0.y+y4.y;
        float t1r=y0.x-y4.x, t1i=y0.y-y4.y;
        float t2r=y2.x+y6.x, t2i=y2.y+y6.y;
        float t3r=y2.x-y6.x, t3i=y2.y-y6.y;
        float E0r=t0r+t2r, E0i=t0i+t2i;
        float E1r=t1r+t3i, E1i=t1i-t3r;
        float E2r=t0r-t2r, E2i=t0i-t2i;
        float E3r=t1r-t3i, E3i=t1i+t3r;
        // O = FFT4(y1,y3,y5,y7)
        float u0r=y1.x+y5.x, u0i=y1.y+y5.y;
        float u1r=y1.x-y5.x, u1i=y1.y-y5.y;
        float u2r=y3.x+y7.x, u2i=y3.y+y7.y;
        float u3r=y3.x-y7.x, u3i=y3.y-y7.y;
        float O0r=u0r+u2r, O0i=u0i+u2i;
        float O1r=u1r+u3i, O1i=u1i-u3r;
        float O2r=u0r-u2r, O2i=u0i-u2i;
        float O3r=u1r-u3i, O3i=u1i+u3r;
        const float RT2 = 0.70710678118654752440f;      // sqrt(2)/2
        float a1r = RT2*(O1r+O1i), a1i = RT2*(O1i-O1r); // W8^1 * O1
        float a2r = O2i,           a2i = -O2r;          // W8^2 * O2 = -i*O2
        float a3r = RT2*(O3i-O3r), a3i = -RT2*(O3r+O3i);// W8^3 * O3
        b[j]      = make_float2(E0r+O0r, E0i+O0i);
        b[j+ 625] = make_float2(E1r+a1r, E1i+a1i);
        b[j+1250] = make_float2(E2r+a2r, E2i+a2i);
        b[j+1875] = make_float2(E3r+a3r, E3i+a3i);
        b[j+2500] = make_float2(E0r-O0r, E0i-O0i);
        b[j+3125] = make_float2(E1r-a1r, E1i-a1i);
        b[j+3750] = make_float2(E2r-a2r, E2i-a2i);
        b[j+4375] = make_float2(E3r-a3r, E3i-a3i);
    }
}

// ---------------- Pass 1: real FFT (10000 via 5000-pack) + log-magnitude ----------------
__global__ __launch_bounds__(FFT_THREADS, 2)
void fft_logabs_kernel(const float* __restrict__ x) {
    extern __shared__ float2 smbuf[];
    float2* pb0 = smbuf;
    float2* pb1 = smbuf + NFFT;
    const int tid = threadIdx.x;
    const size_t row = blockIdx.x;

    // pack: z[n] = x[2n] + i*x[2n+1]
    const float2* xin = (const float2*)(x + row * NFULL);
    for (int n = tid; n < NFFT; n += FFT_THREADS) pb0[n] = xin[n];
    __syncthreads();

    stage_r5<1>  (pb0, pb1, tid); __syncthreads();
    stage_r5<5>  (pb1, pb0, tid); __syncthreads();
    stage_r5<25> (pb0, pb1, tid); __syncthreads();
    stage_r5<125>(pb1, pb0, tid); __syncthreads();
    stage_r8     (pb0, pb1, tid); __syncthreads();
    // Z[k] now lives in pb1

    float* outp = g_xl + row * NFULL;
    for (int k = tid; k <= 2500; k += FFT_THREADS) {
        const int km = (k == 0) ? 0 : (NFFT - k);
        float2 zk  = pb1[k];
        float2 zkm = pb1[km];
        float Er = 0.5f*(zk.x + zkm.x), Ei = 0.5f*(zk.y - zkm.y);
        float Or = 0.5f*(zk.y + zkm.y), Oi = 0.5f*(zkm.x - zk.x);
        float2 w = g_wtab[k];            // exp(-2*pi*i*k/10000)
        float tr = w.x*Or - w.y*Oi;
        float ti = w.x*Oi + w.y*Or;
        float pr = Er + tr, pi = Ei + ti;   // X[k]
        float mr = Er - tr, mi = Ei - ti;   // X[5000+k]; |X[5000+k]| == |X[5000-k]|
        float l1 = 0.5f * logf(pr*pr + pi*pi);
        float l2 = 0.5f * logf(mr*mr + mi*mi);
        outp[k]        = l1;
        outp[5000 - k] = l2;
        if (k > 0) {
            outp[10000 - k] = l1;       // conjugate symmetry of the real-input FFT
            outp[5000 + k]  = l2;
        }
    }
}

// ---------------- Pass 2: per-segment GEMM ----------------
// x2[b,o,s] = relu( sum_{c,k} xl[b,c,s*100+k] * W1[s,o,c,k] + b1[s,o] )
// Grid 200 = (segment s) x (batch half). Block: 256 threads, 128 b-rows, all 32 o.
__global__ __launch_bounds__(256, 2)
void seg_gemm_kernel(const float* __restrict__ W1, const float* __restrict__ b1) {
    extern __shared__ float sm[];
    float* Asm = sm;                        // [128][PAD_A] (100 valid k)
    float* Wsm = sm + GEMM_ROWS * PAD_A;    // [32][PAD_W]
    const int s    = blockIdx.x >> 1;
    const int b0   = (blockIdx.x & 1) * GEMM_ROWS;
    const int tid  = threadIdx.x;
    const int bg   = tid & 31;              // b lane (local b = bg + 32*i, i<4)
    const int og   = tid >> 5;              // warp id 0..7
    const int o0   = og * 4;

    float acc[4][4];
    #pragma unroll
    for (int i = 0; i < 4; i++)
        #pragma unroll
        for (int j = 0; j < 4; j++) acc[i][j] = 0.0f;

    for (int c = 0; c < 20; c++) {
        // A tile: 128 b-rows x 100 k floats (float4, coalesced)
        for (int q = tid; q < GEMM_ROWS*25; q += 256) {
            int b  = q / 25;
            int kq = q % 25;
            float4 v = *(const float4*)(g_xl + ((size_t)(b0 + b)*20 + c)*10000 + s*100 + kq*4);
            *(float4*)(Asm + b*PAD_A + kq*4) = v;
        }
        // W tile: 32 o-rows x 100 k floats
        for (int q = tid; q < 800; q += 256) {
            int o  = q / 25;
            int kq = q % 25;
            float4 v = *(const float4*)(W1 + (((size_t)s*32 + o)*20 + c)*100 + kq*4);
            *(float4*)(Wsm + o*PAD_W + kq*4) = v;
        }
        __syncthreads();

        for (int k = 0; k < 100; k += 4) {
            float4 wv[4];
            #pragma unroll
            for (int j = 0; j < 4; j++)     // warp-uniform address -> LDS broadcast
                wv[j] = *(const float4*)(Wsm + (o0 + j)*PAD_W + k);
            float4 av[4];
            #pragma unroll
            for (int i = 0; i < 4; i++)
                av[i] = *(const float4*)(Asm + (bg + 32*i)*PAD_A + k);
            #pragma unroll
            for (int i = 0; i < 4; i++)
                #pragma unroll
                for (int j = 0; j < 4; j++) {
                    acc[i][j] += av[i].x * wv[j].x;
                    acc[i][j] += av[i].y * wv[j].y;
                    acc[i][j] += av[i].z * wv[j].z;
                    acc[i][j] += av[i].w * wv[j].w;
                }
        }
        __syncthreads();
    }

    #pragma unroll
    for (int i = 0; i < 4; i++) {
        int b = b0 + bg + 32*i;
        #pragma unroll
        for (int j = 0; j < 4; j++) {
            int o = o0 + j;
            float v = acc[i][j] + b1[s*32 + o];
            g_x2[((size_t)b*32 + o)*100 + s] = fmaxf(v, 0.0f);
        }
    }
}

// ---------------- Pass 3: out[b,j] = relu(sum_i x2[b][i] * W2[j][i] + b2[j]) ----------------
__global__ __launch_bounds__(128)
void final_kernel(const float* __restrict__ W2, const float* __restrict__ b2,
                  float* __restrict__ out) {
    const int b   = blockIdx.x;
    const int tid = threadIdx.x;
    float acc[6] = {0.f, 0.f, 0.f, 0.f, 0.f, 0.f};
    const float* xb = g_x2 + (size_t)b * 3200;
    for (int i = tid; i < 3200; i += 128) {
        float v = xb[i];
        #pragma unroll
        for (int j = 0; j < 6; j++) acc[j] += v * W2[j*3200 + i];
    }
    #pragma unroll
    for (int off = 16; off > 0; off >>= 1)
        #pragma unroll
        for (int j = 0; j < 6; j++)
            acc[j] += __shfl_xor_sync(0xFFFFFFFFu, acc[j], off);
    __shared__ float red[4][6];
    if ((tid & 31) == 0) {
        #pragma unroll
        for (int j = 0; j < 6; j++) red[tid >> 5][j] = acc[j];
    }
    __syncthreads();
    if (tid < 6) {
        float t = red[0][tid] + red[1][tid] + red[2][tid] + red[3][tid] + b2[tid];
        out[b*6 + tid] = fmaxf(t, 0.0f);
    }
}

// ---------------- launch ----------------
extern "C" void kernel_launch(void* const* d_in, const int* in_sizes, int n_in,
                              void* d_out, int out_size) {
    (void)in_sizes; (void)n_in; (void)out_size;
    const float* x  = (const float*)d_in[0];
    const float* W1 = (const float*)d_in[1];
    const float* b1 = (const float*)d_in[2];
    const float* W2 = (const float*)d_in[3];
    const float* b2 = (const float*)d_in[4];
    float* out = (float*)d_out;

    cudaFuncSetAttribute(fft_logabs_kernel, cudaFuncAttributeMaxDynamicSharedMemorySize, FFT_SMEM);
    cudaFuncSetAttribute(seg_gemm_kernel,   cudaFuncAttributeMaxDynamicSharedMemorySize, GEMM_SMEM);

    fill_twiddles_kernel<<<79, 128>>>();
    fft_logabs_kernel<<<NROWS, FFT_THREADS, FFT_SMEM>>>(x);
    seg_gemm_kernel<<<200, 256, GEMM_SMEM>>>(W1, b1);
    final_kernel<<<256, 128>>>(W2, b2, out);
}

// round 8
// speedup vs baseline: 1.3322x; 1.0579x over previous
#include <cuda_runtime.h>
#include <math.h>

#define NFFT 5000
#define NFULL 10000
#define NROWS (256*20)          // 5120 FFT rows
#define FFT_THREADS 256
#define FFT_SMEM (4*NFFT*4)     // 80000 bytes: re0,im0,re1,im1

#define PAD_A 108               // 108 % 32 = 12 -> conflict-free float4 lane pattern
#define PAD_W 104
#define GEMM_ROWS 128           // batch rows per block (2 blocks per segment)
#define GEMM_SMEM ((GEMM_ROWS*PAD_A + 32*PAD_W)*4)   // 68608 bytes

// ---------------- scratch (no allocations allowed) ----------------
__device__ float2 d_wtab[NFFT];                 // exp(-2*pi*i*k/5000)
__device__ float  d_xl[(size_t)256*20*10000];   // log|FFT(x)|, layout [b][c][j]
__device__ float  d_x2[(size_t)256*32*100];     // relu(conv1), layout [b][o][s]
__device__ float  d_marker;                     // ncu window-shift dummy target

// ---------------- marker: shifts the ncu -s window onto a heavy kernel ----------------
__global__ void marker_kernel() {
    if (threadIdx.x == 0) d_marker = 1.0f;
}

// ---------------- twiddle table ----------------
__global__ void twiddle_kernel() {
    int k = blockIdx.x * blockDim.x + threadIdx.x;
    if (k < NFFT) {
        double ang = -2.0 * 3.14159265358979323846 * (double)k / (double)NFFT;
        d_wtab[k] = make_float2((float)cos(ang), (float)sin(ang));
    }
}

// ---------------- FFT helpers ----------------
__device__ __forceinline__ float2 cmulf(float2 a, float2 b) {
    return make_float2(a.x*b.x - a.y*b.y, a.x*b.y + a.y*b.x);
}

template<int NS>
__device__ __forceinline__ void radix5_stage(const float* __restrict__ ra, const float* __restrict__ ia,
                                             float* __restrict__ rb, float* __restrict__ ib, int tid) {
    const int STEP = NFFT / (NS * 5);
    for (int j = tid; j < NFFT/5; j += FFT_THREADS) {
        const int m = j % NS;
        const int t = m * STEP;
        float2 w1 = d_wtab[t];
        float2 w2 = d_wtab[2*t];
        float2 w3 = d_wtab[3*t];
        float2 w4 = d_wtab[4*t];
        float2 x0 = make_float2(ra[j],        ia[j]);
        float2 x1 = cmulf(make_float2(ra[j+1000], ia[j+1000]), w1);
        float2 x2 = cmulf(make_float2(ra[j+2000], ia[j+2000]), w2);
        float2 x3 = cmulf(make_float2(ra[j+3000], ia[j+3000]), w3);
        float2 x4 = cmulf(make_float2(ra[j+4000], ia[j+4000]), w4);
        float t1r = x1.x + x4.x, t1i = x1.y + x4.y;
        float t2r = x2.x + x3.x, t2i = x2.y + x3.y;
        float t3r = x1.x - x4.x, t3i = x1.y - x4.y;
        float t4r = x2.x - x3.x, t4i = x2.y - x3.y;
        const float c1 =  0.309016994374947424f;   // cos(2pi/5)
        const float c2 = -0.809016994374947424f;   // cos(4pi/5)
        const float s1 =  0.951056516295153572f;   // sin(2pi/5)
        const float s2 =  0.587785252292473129f;   // sin(4pi/5)
        float y0r = x0.x + t1r + t2r, y0i = x0.y + t1i + t2i;
        float par = x0.x + c1*t1r + c2*t2r, pai = x0.y + c1*t1i + c2*t2i;
        float pbr = s1*t3r + s2*t4r,        pbi = s1*t3i + s2*t4i;
        float pcr = x0.x + c2*t1r + c1*t2r, pci = x0.y + c2*t1i + c1*t2i;
        float pdr = s2*t3r - s1*t4r,        pdi = s2*t3i - s1*t4i;
        const int d = (j / NS) * (NS*5) + m;
        rb[d]        = y0r;       ib[d]        = y0i;
        rb[d +   NS] = par + pbi; ib[d +   NS] = pai - pbr;   // X1 = P - iQ
        rb[d + 2*NS] = pcr + pdi; ib[d + 2*NS] = pci - pdr;   // X2
        rb[d + 3*NS] = pcr - pdi; ib[d + 3*NS] = pci + pdr;   // X3
        rb[d + 4*NS] = par - pbi; ib[d + 4*NS] = pai + pbr;   // X4
    }
}

__device__ __forceinline__ void radix4_stage(const float* __restrict__ ra, const float* __restrict__ ia,
                                             float* __restrict__ rb, float* __restrict__ ib, int tid) {
    // NS = 625, R = 4, STEP = 5000/(625*4) = 2
    for (int j = tid; j < 1250; j += FFT_THREADS) {
        const int m = j % 625;
        const int t = 2 * m;
        float2 w1 = d_wtab[t];
        float2 w2 = d_wtab[2*t];
        float2 w3 = d_wtab[3*t];
        float2 x0 = make_float2(ra[j],        ia[j]);
        float2 x1 = cmulf(make_float2(ra[j+1250], ia[j+1250]), w1);
        float2 x2 = cmulf(make_float2(ra[j+2500], ia[j+2500]), w2);
        float2 x3 = cmulf(make_float2(ra[j+3750], ia[j+3750]), w3);
        float t0r = x0.x + x2.x, t0i = x0.y + x2.y;
        float t1r = x0.x - x2.x, t1i = x0.y - x2.y;
        float t2r = x1.x + x3.x, t2i = x1.y + x3.y;
        float t3r = x1.x - x3.x, t3i = x1.y - x3.y;
        const int d = (j / 625) * 2500 + m;
        rb[d]        = t0r + t2r; ib[d]        = t0i + t2i;   // X0
        rb[d +  625] = t1r + t3i; ib[d +  625] = t1i - t3r;   // X1 = t1 - i*t3
        rb[d + 1250] = t0r - t2r; ib[d + 1250] = t0i - t2i;   // X2
        rb[d + 1875] = t1r - t3i; ib[d + 1875] = t1i + t3r;   // X3
    }
}

__device__ __forceinline__ void radix2_stage(const float* __restrict__ ra, const float* __restrict__ ia,
                                             float* __restrict__ rb, float* __restrict__ ib, int tid) {
    // NS = 2500, R = 2, STEP = 1
    for (int j = tid; j < 2500; j += FFT_THREADS) {
        float2 w = d_wtab[j];
        float2 a = make_float2(ra[j],        ia[j]);
        float2 b = cmulf(make_float2(ra[j+2500], ia[j+2500]), w);
        rb[j]        = a.x + b.x; ib[j]        = a.y + b.y;
        rb[j + 2500] = a.x - b.x; ib[j + 2500] = a.y - b.y;
    }
}

// ---------------- Pass 1: per-row real FFT (length 10000 via 5000-pack) + log|.| ----------------
__global__ __launch_bounds__(FFT_THREADS, 2)
void fft_logabs_kernel(const float* __restrict__ x) {
    extern __shared__ float sm[];
    float* re0 = sm;
    float* im0 = sm + NFFT;
    float* re1 = sm + 2*NFFT;
    float* im1 = sm + 3*NFFT;
    const int tid = threadIdx.x;
    const size_t row = blockIdx.x;

    // pack: z[n] = x[2n] + i*x[2n+1]
    const float2* xin = (const float2*)(x + row * NFULL);
    for (int n = tid; n < NFFT; n += FFT_THREADS) {
        float2 v = xin[n];
        re0[n] = v.x; im0[n] = v.y;
    }
    __syncthreads();

    radix5_stage<1>  (re0, im0, re1, im1, tid); __syncthreads();
    radix5_stage<5>  (re1, im1, re0, im0, tid); __syncthreads();
    radix5_stage<25> (re0, im0, re1, im1, tid); __syncthreads();
    radix5_stage<125>(re1, im1, re0, im0, tid); __syncthreads();
    radix4_stage     (re0, im0, re1, im1, tid); __syncthreads();
    radix2_stage     (re1, im1, re0, im0, tid); __syncthreads();
    // result Z[k] in (re0, im0)

    float* outp = d_xl + row * NFULL;
    for (int k = tid; k <= 2500; k += FFT_THREADS) {
        const int km = (k == 0) ? 0 : (NFFT - k);
        float ar = re0[k],  ai = im0[k];
        float br = re0[km], bi = im0[km];
        // E = (Z[k] + conj(Z[-k]))/2 ; O = (Z[k] - conj(Z[-k]))/(2i)
        float Er = 0.5f*(ar + br), Ei = 0.5f*(ai - bi);
        float Or = 0.5f*(ai + bi), Oi = 0.5f*(br - ar);
        // W = exp(-2*pi*i*k/10000) = exp(-i*pi*k/5000)
        float s, c;
        sincospif(-(float)k * (1.0f/5000.0f), &s, &c);
        float tr = c*Or - s*Oi;
        float ti = c*Oi + s*Or;
        float pr = Er + tr, pi = Ei + ti;   // X[k]
        float mr = Er - tr, mi = Ei - ti;   // X[5000+k]; |X[5000+k]| == |X[5000-k]|
        float l1 = 0.5f * logf(pr*pr + pi*pi);
        float l2 = 0.5f * logf(mr*mr + mi*mi);
        outp[k]        = l1;
        outp[5000 - k] = l2;
        if (k > 0) {
            outp[10000 - k] = l1;   // conj symmetry of real-input FFT
            outp[5000 + k]  = l2;
        }
    }
}

// ---------------- Pass 2: per-segment GEMM ----------------
// x2[b,o,s] = relu( sum_{c,k} xl[b,c,s*100+k] * W1[s,o,c,k] + b1[s,o] )
// Grid: 200 blocks = (segment s) x (batch half). Each block: 128 b-rows, all 32 o.
__global__ __launch_bounds__(256, 2)
void seg_gemm_kernel(const float* __restrict__ W1, const float* __restrict__ b1) {
    extern __shared__ float sm[];
    float* Asm = sm;                        // [128][PAD_A] (100 valid k)
    float* Wsm = sm + GEMM_ROWS * PAD_A;    // [32][PAD_W]
    const int s    = blockIdx.x >> 1;
    const int b0   = (blockIdx.x & 1) * GEMM_ROWS;
    const int tid  = threadIdx.x;
    const int bg   = tid & 31;              // b lane (local b = bg + 32*i, i<4)
    const int og   = tid >> 5;              // 0..7
    const int o0   = og * 4;

    float acc[4][4];
    #pragma unroll
    for (int i = 0; i < 4; i++)
        #pragma unroll
        for (int j = 0; j < 4; j++) acc[i][j] = 0.0f;

    for (int c = 0; c < 20; c++) {
        // load A tile: 128 b-rows x 100 k floats (float4, coalesced)
        for (int q = tid; q < GEMM_ROWS*25; q += 256) {
            int b  = q / 25;
            int kq = q % 25;
            float4 v = *(const float4*)(d_xl + ((size_t)(b0 + b)*20 + c)*10000 + s*100 + kq*4);
            *(float4*)(Asm + b*PAD_A + kq*4) = v;
        }
        // load W tile: 32 o-rows x 100 k floats
        for (int q = tid; q < 800; q += 256) {
            int o  = q / 25;
            int kq = q % 25;
            float4 v = *(const float4*)(W1 + (((size_t)s*32 + o)*20 + c)*100 + kq*4);
            *(float4*)(Wsm + o*PAD_W + kq*4) = v;
        }
        __syncthreads();

        for (int k = 0; k < 100; k += 4) {
            float4 wv[4];
            #pragma unroll
            for (int j = 0; j < 4; j++)     // warp-uniform (o0 per-warp) -> LDS broadcast
                wv[j] = *(const float4*)(Wsm + (o0 + j)*PAD_W + k);
            float4 av[4];
            #pragma unroll
            for (int i = 0; i < 4; i++)
                av[i] = *(const float4*)(Asm + (bg + 32*i)*PAD_A + k);
            #pragma unroll
            for (int i = 0; i < 4; i++)
                #pragma unroll
                for (int j = 0; j < 4; j++) {
                    acc[i][j] += av[i].x * wv[j].x;
                    acc[i][j] += av[i].y * wv[j].y;
                    acc[i][j] += av[i].z * wv[j].z;
                    acc[i][j] += av[i].w * wv[j].w;
                }
        }
        __syncthreads();
    }

    #pragma unroll
    for (int i = 0; i < 4; i++) {
        int b = b0 + bg + 32*i;
        #pragma unroll
        for (int j = 0; j < 4; j++) {
            int o = o0 + j;
            float v = acc[i][j] + b1[s*32 + o];
            d_x2[((size_t)b*32 + o)*100 + s] = fmaxf(v, 0.0f);
        }
    }
}

// ---------------- Pass 3: out[b,j] = relu(sum_i x2[b][i] * W2[j][i] + b2[j]) ----------------
__global__ __launch_bounds__(128)
void final_kernel(const float* __restrict__ W2, const float* __restrict__ b2,
                  float* __restrict__ out) {
    const int b   = blockIdx.x;
    const int tid = threadIdx.x;
    float acc[6] = {0.f, 0.f, 0.f, 0.f, 0.f, 0.f};
    const float* xb = d_x2 + (size_t)b * 3200;
    for (int i = tid; i < 3200; i += 128) {
        float v = xb[i];
        #pragma unroll
        for (int j = 0; j < 6; j++) acc[j] += v * W2[j*3200 + i];
    }
    #pragma unroll
    for (int off = 16; off > 0; off >>= 1)
        #pragma unroll
        for (int j = 0; j < 6; j++)
            acc[j] += __shfl_xor_sync(0xFFFFFFFFu, acc[j], off);
    __shared__ float red[4][6];
    if ((tid & 31) == 0) {
        #pragma unroll
        for (int j = 0; j < 6; j++) red[tid >> 5][j] = acc[j];
    }
    __syncthreads();
    if (tid < 6) {
        float t = red[0][tid] + red[1][tid] + red[2][tid] + red[3][tid] + b2[tid];
        out[b*6 + tid] = fmaxf(t, 0.0f);
    }
}

// ---------------- launch ----------------
extern "C" void kernel_launch(void* const* d_in, const int* in_sizes, int n_in,
                              void* d_out, int out_size) {
    (void)in_sizes; (void)n_in; (void)out_size;
    const float* x  = (const float*)d_in[0];
    const float* W1 = (const float*)d_in[1];
    const float* b1 = (const float*)d_in[2];
    const float* W2 = (const float*)d_in[3];
    const float* b2 = (const float*)d_in[4];
    float* out = (float*)d_out;

    cudaFuncSetAttribute(fft_logabs_kernel, cudaFuncAttributeMaxDynamicSharedMemorySize, FFT_SMEM);
    cudaFuncSetAttribute(seg_gemm_kernel,   cudaFuncAttributeMaxDynamicSharedMemorySize, GEMM_SMEM);

    marker_kernel<<<1, 32>>>();   // shifts ncu -s window onto fft (C=7) or gemm (C=3)
    twiddle_kernel<<<20, 256>>>();
    fft_logabs_kernel<<<NROWS, FFT_THREADS, FFT_SMEM>>>(x);
    seg_gemm_kernel<<<200, 256, GEMM_SMEM>>>(W1, b1);
    final_kernel<<<256, 128>>>(W2, b2, out);
}

// round 9
// speedup vs baseline: 1.4303x; 1.0736x over previous
#include <cuda_runtime.h>
#include <math.h>

#define NFFT 5000
#define NFULL 10000
#define NROWS (256*20)          // 5120 FFT rows
#define FFT_THREADS 256
#define FFT_SMEM (4*NFFT*4)     // 80000 bytes: re0,im0,re1,im1

#define PAD_A 108               // 108 % 32 = 12 -> conflict-free float4 lane pattern
#define PAD_W 104
#define GEMM_ROWS 64            // batch rows per block (4 blocks per segment)
#define GEMM_SMEM ((GEMM_ROWS*PAD_A + 32*PAD_W)*4)   // 40960 bytes

// ---------------- scratch (no allocations allowed) ----------------
__device__ float2 d_wtab[NFFT];                 // exp(-2*pi*i*k/5000)
__device__ float  d_xl[(size_t)256*20*10000];   // log|FFT(x)|, layout [b][c][j]
__device__ float  d_x2[(size_t)256*32*100];     // relu(conv1), layout [b][o][s]
__device__ float  d_marker;                     // ncu window-shift dummy target

// ---------------- markers: shift the ncu capture window onto fft (index 3) ----------------
__global__ void marker_kernel() {
    if (threadIdx.x == 0) d_marker = 1.0f;
}
__global__ void marker2_kernel() {
    if (threadIdx.x == 0) d_marker = 2.0f;
}

// ---------------- twiddle table ----------------
__global__ void twiddle_kernel() {
    int k = blockIdx.x * blockDim.x + threadIdx.x;
    if (k < NFFT) {
        double ang = -2.0 * 3.14159265358979323846 * (double)k / (double)NFFT;
        d_wtab[k] = make_float2((float)cos(ang), (float)sin(ang));
    }
}

// ---------------- FFT helpers ----------------
__device__ __forceinline__ float2 cmulf(float2 a, float2 b) {
    return make_float2(a.x*b.x - a.y*b.y, a.x*b.y + a.y*b.x);
}

template<int NS>
__device__ __forceinline__ void radix5_stage(const float* __restrict__ ra, const float* __restrict__ ia,
                                             float* __restrict__ rb, float* __restrict__ ib, int tid) {
    const int STEP = NFFT / (NS * 5);
    for (int j = tid; j < NFFT/5; j += FFT_THREADS) {
        const int m = j % NS;
        const int t = m * STEP;
        float2 w1 = d_wtab[t];
        float2 w2 = d_wtab[2*t];
        float2 w3 = d_wtab[3*t];
        float2 w4 = d_wtab[4*t];
        float2 x0 = make_float2(ra[j],        ia[j]);
        float2 x1 = cmulf(make_float2(ra[j+1000], ia[j+1000]), w1);
        float2 x2 = cmulf(make_float2(ra[j+2000], ia[j+2000]), w2);
        float2 x3 = cmulf(make_float2(ra[j+3000], ia[j+3000]), w3);
        float2 x4 = cmulf(make_float2(ra[j+4000], ia[j+4000]), w4);
        float t1r = x1.x + x4.x, t1i = x1.y + x4.y;
        float t2r = x2.x + x3.x, t2i = x2.y + x3.y;
        float t3r = x1.x - x4.x, t3i = x1.y - x4.y;
        float t4r = x2.x - x3.x, t4i = x2.y - x3.y;
        const float c1 =  0.309016994374947424f;   // cos(2pi/5)
        const float c2 = -0.809016994374947424f;   // cos(4pi/5)
        const float s1 =  0.951056516295153572f;   // sin(2pi/5)
        const float s2 =  0.587785252292473129f;   // sin(4pi/5)
        float y0r = x0.x + t1r + t2r, y0i = x0.y + t1i + t2i;
        float par = x0.x + c1*t1r + c2*t2r, pai = x0.y + c1*t1i + c2*t2i;
        float pbr = s1*t3r + s2*t4r,        pbi = s1*t3i + s2*t4i;
        float pcr = x0.x + c2*t1r + c1*t2r, pci = x0.y + c2*t1i + c1*t2i;
        float pdr = s2*t3r - s1*t4r,        pdi = s2*t3i - s1*t4i;
        const int d = (j / NS) * (NS*5) + m;
        rb[d]        = y0r;       ib[d]        = y0i;
        rb[d +   NS] = par + pbi; ib[d +   NS] = pai - pbr;   // X1 = P - iQ
        rb[d + 2*NS] = pcr + pdi; ib[d + 2*NS] = pci - pdr;   // X2
        rb[d + 3*NS] = pcr - pdi; ib[d + 3*NS] = pci + pdr;   // X3
        rb[d + 4*NS] = par - pbi; ib[d + 4*NS] = pai + pbr;   // X4
    }
}

__device__ __forceinline__ void radix4_stage(const float* __restrict__ ra, const float* __restrict__ ia,
                                             float* __restrict__ rb, float* __restrict__ ib, int tid) {
    // NS = 625, R = 4, STEP = 5000/(625*4) = 2
    for (int j = tid; j < 1250; j += FFT_THREADS) {
        const int m = j % 625;
        const int t = 2 * m;
        float2 w1 = d_wtab[t];
        float2 w2 = d_wtab[2*t];
        float2 w3 = d_wtab[3*t];
        float2 x0 = make_float2(ra[j],        ia[j]);
        float2 x1 = cmulf(make_float2(ra[j+1250], ia[j+1250]), w1);
        float2 x2 = cmulf(make_float2(ra[j+2500], ia[j+2500]), w2);
        float2 x3 = cmulf(make_float2(ra[j+3750], ia[j+3750]), w3);
        float t0r = x0.x + x2.x, t0i = x0.y + x2.y;
        float t1r = x0.x - x2.x, t1i = x0.y - x2.y;
        float t2r = x1.x + x3.x, t2i = x1.y + x3.y;
        float t3r = x1.x - x3.x, t3i = x1.y - x3.y;
        const int d = (j / 625) * 2500 + m;
        rb[d]        = t0r + t2r; ib[d]        = t0i + t2i;   // X0
        rb[d +  625] = t1r + t3i; ib[d +  625] = t1i - t3r;   // X1 = t1 - i*t3
        rb[d + 1250] = t0r - t2r; ib[d + 1250] = t0i - t2i;   // X2
        rb[d + 1875] = t1r - t3i; ib[d + 1875] = t1i + t3r;   // X3
    }
}

__device__ __forceinline__ void radix2_stage(const float* __restrict__ ra, const float* __restrict__ ia,
                                             float* __restrict__ rb, float* __restrict__ ib, int tid) {
    // NS = 2500, R = 2, STEP = 1
    for (int j = tid; j < 2500; j += FFT_THREADS) {
        float2 w = d_wtab[j];
        float2 a = make_float2(ra[j],        ia[j]);
        float2 b = cmulf(make_float2(ra[j+2500], ia[j+2500]), w);
        rb[j]        = a.x + b.x; ib[j]        = a.y + b.y;
        rb[j + 2500] = a.x - b.x; ib[j + 2500] = a.y - b.y;
    }
}

// ---------------- Pass 1: per-row real FFT (length 10000 via 5000-pack) + log|.| ----------------
__global__ __launch_bounds__(FFT_THREADS, 2)
void fft_logabs_kernel(const float* __restrict__ x) {
    extern __shared__ float sm[];
    float* re0 = sm;
    float* im0 = sm + NFFT;
    float* re1 = sm + 2*NFFT;
    float* im1 = sm + 3*NFFT;
    const int tid = threadIdx.x;
    const size_t row = blockIdx.x;

    // pack: z[n] = x[2n] + i*x[2n+1]
    const float2* xin = (const float2*)(x + row * NFULL);
    for (int n = tid; n < NFFT; n += FFT_THREADS) {
        float2 v = xin[n];
        re0[n] = v.x; im0[n] = v.y;
    }
    __syncthreads();

    radix5_stage<1>  (re0, im0, re1, im1, tid); __syncthreads();
    radix5_stage<5>  (re1, im1, re0, im0, tid); __syncthreads();
    radix5_stage<25> (re0, im0, re1, im1, tid); __syncthreads();
    radix5_stage<125>(re1, im1, re0, im0, tid); __syncthreads();
    radix4_stage     (re0, im0, re1, im1, tid); __syncthreads();
    radix2_stage     (re1, im1, re0, im0, tid); __syncthreads();
    // result Z[k] in (re0, im0)

    float* outp = d_xl + row * NFULL;
    for (int k = tid; k <= 2500; k += FFT_THREADS) {
        const int km = (k == 0) ? 0 : (NFFT - k);
        float ar = re0[k],  ai = im0[k];
        float br = re0[km], bi = im0[km];
        // E = (Z[k] + conj(Z[-k]))/2 ; O = (Z[k] - conj(Z[-k]))/(2i)
        float Er = 0.5f*(ar + br), Ei = 0.5f*(ai - bi);
        float Or = 0.5f*(ai + bi), Oi = 0.5f*(br - ar);
        // W = exp(-2*pi*i*k/10000) = exp(-i*pi*k/5000)
        float s, c;
        sincospif(-(float)k * (1.0f/5000.0f), &s, &c);
        float tr = c*Or - s*Oi;
        float ti = c*Oi + s*Or;
        float pr = Er + tr, pi = Ei + ti;   // X[k]
        float mr = Er - tr, mi = Ei - ti;   // X[5000+k]; |X[5000+k]| == |X[5000-k]|
        float l1 = 0.5f * logf(pr*pr + pi*pi);
        float l2 = 0.5f * logf(mr*mr + mi*mi);
        outp[k]        = l1;
        outp[5000 - k] = l2;
        if (k > 0) {
            outp[10000 - k] = l1;   // conj symmetry of real-input FFT
            outp[5000 + k]  = l2;
        }
    }
}

// ---------------- Pass 2: per-segment GEMM, batch split 4 ways ----------------
// x2[b,o,s] = relu( sum_{c,k} xl[b,c,s*100+k] * W1[s,o,c,k] + b1[s,o] )
// Grid 400 = (segment s) x (batch quarter). Block: 256 threads, 64 b-rows, all 32 o.
__global__ __launch_bounds__(256)
void seg_gemm_kernel(const float* __restrict__ W1, const float* __restrict__ b1) {
    extern __shared__ float sm[];
    float* Asm = sm;                        // [64][PAD_A] (100 valid k)
    float* Wsm = sm + GEMM_ROWS * PAD_A;    // [32][PAD_W]
    const int s    = blockIdx.x >> 2;
    const int b0   = (blockIdx.x & 3) * GEMM_ROWS;
    const int tid  = threadIdx.x;
    const int bg   = tid & 31;              // b lane (local b = bg + 32*i, i<2)
    const int og   = tid >> 5;              // 0..7
    const int o0   = og * 4;

    float acc[2][4];
    #pragma unroll
    for (int i = 0; i < 2; i++)
        #pragma unroll
        for (int j = 0; j < 4; j++) acc[i][j] = 0.0f;

    for (int c = 0; c < 20; c++) {
        // load A tile: 64 b-rows x 100 k floats (float4, coalesced)
        for (int q = tid; q < GEMM_ROWS*25; q += 256) {
            int b  = q / 25;
            int kq = q % 25;
            float4 v = *(const float4*)(d_xl + ((size_t)(b0 + b)*20 + c)*10000 + s*100 + kq*4);
            *(float4*)(Asm + b*PAD_A + kq*4) = v;
        }
        // load W tile: 32 o-rows x 100 k floats
        for (int q = tid; q < 800; q += 256) {
            int o  = q / 25;
            int kq = q % 25;
            float4 v = *(const float4*)(W1 + (((size_t)s*32 + o)*20 + c)*100 + kq*4);
            *(float4*)(Wsm + o*PAD_W + kq*4) = v;
        }
        __syncthreads();

        for (int k = 0; k < 100; k += 4) {
            float4 wv[4];
            #pragma unroll
            for (int j = 0; j < 4; j++)     // warp-uniform (o0 per-warp) -> LDS broadcast
                wv[j] = *(const float4*)(Wsm + (o0 + j)*PAD_W + k);
            float4 av[2];
            #pragma unroll
            for (int i = 0; i < 2; i++)
                av[i] = *(const float4*)(Asm + (bg + 32*i)*PAD_A + k);
            #pragma unroll
            for (int i = 0; i < 2; i++)
                #pragma unroll
                for (int j = 0; j < 4; j++) {
                    acc[i][j] += av[i].x * wv[j].x;
                    acc[i][j] += av[i].y * wv[j].y;
                    acc[i][j] += av[i].z * wv[j].z;
                    acc[i][j] += av[i].w * wv[j].w;
                }
        }
        __syncthreads();
    }

    #pragma unroll
    for (int i = 0; i < 2; i++) {
        int b = b0 + bg + 32*i;
        #pragma unroll
        for (int j = 0; j < 4; j++) {
            int o = o0 + j;
            float v = acc[i][j] + b1[s*32 + o];
            d_x2[((size_t)b*32 + o)*100 + s] = fmaxf(v, 0.0f);
        }
    }
}

// ---------------- Pass 3: out[b,j] = relu(sum_i x2[b][i] * W2[j][i] + b2[j]) ----------------
__global__ __launch_bounds__(128)
void final_kernel(const float* __restrict__ W2, const float* __restrict__ b2,
                  float* __restrict__ out) {
    const int b   = blockIdx.x;
    const int tid = threadIdx.x;
    float acc[6] = {0.f, 0.f, 0.f, 0.f, 0.f, 0.f};
    const float* xb = d_x2 + (size_t)b * 3200;
    for (int i = tid; i < 3200; i += 128) {
        float v = xb[i];
        #pragma unroll
        for (int j = 0; j < 6; j++) acc[j] += v * W2[j*3200 + i];
    }
    #pragma unroll
    for (int off = 16; off > 0; off >>= 1)
        #pragma unroll
        for (int j = 0; j < 6; j++)
            acc[j] += __shfl_xor_sync(0xFFFFFFFFu, acc[j], off);
    __shared__ float red[4][6];
    if ((tid & 31) == 0) {
        #pragma unroll
        for (int j = 0; j < 6; j++) red[tid >> 5][j] = acc[j];
    }
    __syncthreads();
    if (tid < 6) {
        float t = red[0][tid] + red[1][tid] + red[2][tid] + red[3][tid] + b2[tid];
        out[b*6 + tid] = fmaxf(t, 0.0f);
    }
}

// ---------------- launch ----------------
extern "C" void kernel_launch(void* const* d_in, const int* in_sizes, int n_in,
                              void* d_out, int out_size) {
    (void)in_sizes; (void)n_in; (void)out_size;
    const float* x  = (const float*)d_in[0];
    const float* W1 = (const float*)d_in[1];
    const float* b1 = (const float*)d_in[2];
    const float* W2 = (const float*)d_in[3];
    const float* b2 = (const float*)d_in[4];
    float* out = (float*)d_out;

    cudaFuncSetAttribute(fft_logabs_kernel, cudaFuncAttributeMaxDynamicSharedMemorySize, FFT_SMEM);
    cudaFuncSetAttribute(seg_gemm_kernel,   cudaFuncAttributeMaxDynamicSharedMemorySize, GEMM_SMEM);

    marker_kernel<<<1, 32>>>();   // index 0
    marker2_kernel<<<1, 32>>>();  // index 1 — shifts capture (in-call index 3) onto fft
    twiddle_kernel<<<20, 256>>>();                              // index 2
    fft_logabs_kernel<<<NROWS, FFT_THREADS, FFT_SMEM>>>(x);     // index 3 <- ncu target
    seg_gemm_kernel<<<400, 256, GEMM_SMEM>>>(W1, b1);           // index 4
    final_kernel<<<256, 128>>>(W2, b2, out);                    // index 5
}

// round 12
// speedup vs baseline: 1.7067x; 1.1933x over previous
#include <cuda_runtime.h>
#include <math.h>

// FFTConv pipeline — third submission of the 512-thread FFT occupancy experiment
// (two prior attempts never executed: broker-side container failures).
// Baseline measured: total 671.7us, fft 448.6us @256 threads (occ 24.5%, issue 30.4%).

#define NFFT 5000
#define NFULL 10000
#define NROWS (256*20)          // 5120 FFT rows (256 batch x 20 channels)
#define FFT_THREADS 512
#define FFT_SMEM (4*NFFT*4)     // 80000 B: re0, im0, re1, im1 ping-pong planes

#define PAD_A 108               // 108 mod 32 = 12 -> conflict-free float4 lane pattern
#define PAD_W 104
#define GEMM_ROWS 64            // batch rows per block (4 blocks per segment)
#define GEMM_SMEM ((GEMM_ROWS*PAD_A + 32*PAD_W)*4)   // 40960 B

// ------------- device-global scratch (heap allocation is prohibited) -------------
__device__ float2 tw_table[NFFT];                // exp(-2*pi*i*k/5000)
__device__ float  buf_logmag[(size_t)256*20*10000]; // log|FFT(x)|, [b][c][j]
__device__ float  buf_hidden[(size_t)256*32*100];   // relu(conv1), [b][o][s]
__device__ float  sink_word;                     // dummy store target for shim kernels

// ------------- capture-window shims (ncu profiles in-call launch index 3) -------------
__global__ void shim_one() {
    if (threadIdx.x == 0) sink_word = 41.0f;
}
__global__ void shim_two() {
    if (threadIdx.x == 0) sink_word = 42.0f;
}

// ------------- twiddle-table initialization -------------
__global__ void init_twiddles() {
    int k = blockIdx.x * blockDim.x + threadIdx.x;
    if (k < NFFT) {
        double ang = -2.0 * 3.14159265358979323846 * (double)k / (double)NFFT;
        tw_table[k] = make_float2((float)cos(ang), (float)sin(ang));
    }
}

// ------------- complex multiply -------------
__device__ __forceinline__ float2 cxmul(float2 a, float2 b) {
    return make_float2(a.x*b.x - a.y*b.y, a.x*b.y + a.y*b.x);
}

// ------------- Stockham radix-5 stage -------------
template<int NS>
__device__ __forceinline__ void stage_r5(const float* __restrict__ ra, const float* __restrict__ ia,
                                         float* __restrict__ rb, float* __restrict__ ib, int tid) {
    const int STEP = NFFT / (NS * 5);
    for (int j = tid; j < NFFT/5; j += FFT_THREADS) {
        const int m = j % NS;
        const int t = m * STEP;
        float2 w1 = tw_table[t];
        float2 w2 = tw_table[2*t];
        float2 w3 = tw_table[3*t];
        float2 w4 = tw_table[4*t];
        float2 x0 = make_float2(ra[j],        ia[j]);
        float2 x1 = cxmul(make_float2(ra[j+1000], ia[j+1000]), w1);
        float2 x2 = cxmul(make_float2(ra[j+2000], ia[j+2000]), w2);
        float2 x3 = cxmul(make_float2(ra[j+3000], ia[j+3000]), w3);
        float2 x4 = cxmul(make_float2(ra[j+4000], ia[j+4000]), w4);
        float t1r = x1.x + x4.x, t1i = x1.y + x4.y;
        float t2r = x2.x + x3.x, t2i = x2.y + x3.y;
        float t3r = x1.x - x4.x, t3i = x1.y - x4.y;
        float t4r = x2.x - x3.x, t4i = x2.y - x3.y;
        const float c1 =  0.309016994374947424f;   // cos(2pi/5)
        const float c2 = -0.809016994374947424f;   // cos(4pi/5)
        const float s1 =  0.951056516295153572f;   // sin(2pi/5)
        const float s2 =  0.587785252292473129f;   // sin(4pi/5)
        float y0r = x0.x + t1r + t2r, y0i = x0.y + t1i + t2i;
        float par = x0.x + c1*t1r + c2*t2r, pai = x0.y + c1*t1i + c2*t2i;
        float pbr = s1*t3r + s2*t4r,        pbi = s1*t3i + s2*t4i;
        float pcr = x0.x + c2*t1r + c1*t2r, pci = x0.y + c2*t1i + c1*t2i;
        float pdr = s2*t3r - s1*t4r,        pdi = s2*t3i - s1*t4i;
        const int d = (j / NS) * (NS*5) + m;
        rb[d]        = y0r;       ib[d]        = y0i;
        rb[d +   NS] = par + pbi; ib[d +   NS] = pai - pbr;   // X1 = P - iQ
        rb[d + 2*NS] = pcr + pdi; ib[d + 2*NS] = pci - pdr;   // X2
        rb[d + 3*NS] = pcr - pdi; ib[d + 3*NS] = pci + pdr;   // X3
        rb[d + 4*NS] = par - pbi; ib[d + 4*NS] = pai + pbr;   // X4
    }
}

// ------------- Stockham radix-4 stage (NS=625, STEP=2) -------------
__device__ __forceinline__ void stage_r4(const float* __restrict__ ra, const float* __restrict__ ia,
                                         float* __restrict__ rb, float* __restrict__ ib, int tid) {
    for (int j = tid; j < 1250; j += FFT_THREADS) {
        const int m = j % 625;
        const int t = 2 * m;
        float2 w1 = tw_table[t];
        float2 w2 = tw_table[2*t];
        float2 w3 = tw_table[3*t];
        float2 x0 = make_float2(ra[j],        ia[j]);
        float2 x1 = cxmul(make_float2(ra[j+1250], ia[j+1250]), w1);
        float2 x2 = cxmul(make_float2(ra[j+2500], ia[j+2500]), w2);
        float2 x3 = cxmul(make_float2(ra[j+3750], ia[j+3750]), w3);
        float t0r = x0.x + x2.x, t0i = x0.y + x2.y;
        float t1r = x0.x - x2.x, t1i = x0.y - x2.y;
        float t2r = x1.x + x3.x, t2i = x1.y + x3.y;
        float t3r = x1.x - x3.x, t3i = x1.y - x3.y;
        const int d = (j / 625) * 2500 + m;
        rb[d]        = t0r + t2r; ib[d]        = t0i + t2i;   // X0
        rb[d +  625] = t1r + t3i; ib[d +  625] = t1i - t3r;   // X1 = t1 - i*t3
        rb[d + 1250] = t0r - t2r; ib[d + 1250] = t0i - t2i;   // X2
        rb[d + 1875] = t1r - t3i; ib[d + 1875] = t1i + t3r;   // X3
    }
}

// ------------- Stockham radix-2 stage (NS=2500, STEP=1) -------------
__device__ __forceinline__ void stage_r2(const float* __restrict__ ra, const float* __restrict__ ia,
                                         float* __restrict__ rb, float* __restrict__ ib, int tid) {
    for (int j = tid; j < 2500; j += FFT_THREADS) {
        float2 w = tw_table[j];
        float2 a = make_float2(ra[j],        ia[j]);
        float2 b = cxmul(make_float2(ra[j+2500], ia[j+2500]), w);
        rb[j]        = a.x + b.x; ib[j]        = a.y + b.y;
        rb[j + 2500] = a.x - b.x; ib[j + 2500] = a.y - b.y;
    }
}

// ------------- Pass 1: real FFT of length 10000 (packed 5000-point) + log|.| -------------
__global__ __launch_bounds__(FFT_THREADS, 2)
void fft_logabs_kernel(const float* __restrict__ x) {
    extern __shared__ float sm[];
    float* re0 = sm;
    float* im0 = sm + NFFT;
    float* re1 = sm + 2*NFFT;
    float* im1 = sm + 3*NFFT;
    const int tid = threadIdx.x;
    const size_t row = blockIdx.x;

    // pack two real samples per complex point: z[n] = x[2n] + i*x[2n+1]
    const float2* xin = (const float2*)(x + row * NFULL);
    for (int n = tid; n < NFFT; n += FFT_THREADS) {
        float2 v = xin[n];
        re0[n] = v.x; im0[n] = v.y;
    }
    __syncthreads();

    stage_r5<1>  (re0, im0, re1, im1, tid); __syncthreads();
    stage_r5<5>  (re1, im1, re0, im0, tid); __syncthreads();
    stage_r5<25> (re0, im0, re1, im1, tid); __syncthreads();
    stage_r5<125>(re1, im1, re0, im0, tid); __syncthreads();
    stage_r4     (re0, im0, re1, im1, tid); __syncthreads();
    stage_r2     (re1, im1, re0, im0, tid); __syncthreads();
    // Z[k] resident in (re0, im0)

    float* outp = buf_logmag + row * NFULL;
    for (int k = tid; k <= 2500; k += FFT_THREADS) {
        const int km = (k == 0) ? 0 : (NFFT - k);
        float ar = re0[k],  ai = im0[k];
        float br = re0[km], bi = im0[km];
        // untangle: E = (Z[k] + conj(Z[-k]))/2 ; O = (Z[k] - conj(Z[-k]))/(2i)
        float Er = 0.5f*(ar + br), Ei = 0.5f*(ai - bi);
        float Or = 0.5f*(ai + bi), Oi = 0.5f*(br - ar);
        // W = exp(-2*pi*i*k/10000)
        float s, c;
        sincospif(-(float)k * (1.0f/5000.0f), &s, &c);
        float tr = c*Or - s*Oi;
        float ti = c*Oi + s*Or;
        float pr = Er + tr, pi = Ei + ti;   // X[k]
        float mr = Er - tr, mi = Ei - ti;   // X[5000+k]; |X[5000+k]| == |X[5000-k]|
        float l1 = 0.5f * logf(pr*pr + pi*pi);
        float l2 = 0.5f * logf(mr*mr + mi*mi);
        outp[k]        = l1;
        outp[5000 - k] = l2;
        if (k > 0) {
            outp[10000 - k] = l1;   // real-input conjugate symmetry
            outp[5000 + k]  = l2;
        }
    }
}

// ------------- Pass 2: per-segment GEMM, batch quartered -------------
// hidden[b,o,s] = relu( sum_{c,k} logmag[b,c,s*100+k] * W1[s,o,c,k] + b1[s,o] )
// Grid 400 = segment x batch-quarter. 256 threads; 64 b-rows; all 32 o.
__global__ __launch_bounds__(256)
void seg_gemm_kernel(const float* __restrict__ W1, const float* __restrict__ b1) {
    extern __shared__ float sm[];
    float* Asm = sm;                        // [64][PAD_A] (100 valid k)
    float* Wsm = sm + GEMM_ROWS * PAD_A;    // [32][PAD_W]
    const int s    = blockIdx.x >> 2;
    const int b0   = (blockIdx.x & 3) * GEMM_ROWS;
    const int tid  = threadIdx.x;
    const int bg   = tid & 31;              // lane -> local batch row (bg + 32*i)
    const int og   = tid >> 5;              // warp -> output-channel group
    const int o0   = og * 4;

    float acc[2][4];
    #pragma unroll
    for (int i = 0; i < 2; i++)
        #pragma unroll
        for (int j = 0; j < 4; j++) acc[i][j] = 0.0f;

    for (int c = 0; c < 20; c++) {
        // A tile: 64 rows x 100 floats, float4 coalesced
        for (int q = tid; q < GEMM_ROWS*25; q += 256) {
            int b  = q / 25;
            int kq = q % 25;
            float4 v = *(const float4*)(buf_logmag + ((size_t)(b0 + b)*20 + c)*10000 + s*100 + kq*4);
            *(float4*)(Asm + b*PAD_A + kq*4) = v;
        }
        // W tile: 32 rows x 100 floats
        for (int q = tid; q < 800; q += 256) {
            int o  = q / 25;
            int kq = q % 25;
            float4 v = *(const float4*)(W1 + (((size_t)s*32 + o)*20 + c)*100 + kq*4);
            *(float4*)(Wsm + o*PAD_W + kq*4) = v;
        }
        __syncthreads();

        for (int k = 0; k < 100; k += 4) {
            float4 wv[4];
            #pragma unroll
            for (int j = 0; j < 4; j++)     // warp-uniform address -> broadcast read
                wv[j] = *(const float4*)(Wsm + (o0 + j)*PAD_W + k);
            float4 av[2];
            #pragma unroll
            for (int i = 0; i < 2; i++)
                av[i] = *(const float4*)(Asm + (bg + 32*i)*PAD_A + k);
            #pragma unroll
            for (int i = 0; i < 2; i++)
                #pragma unroll
                for (int j = 0; j < 4; j++) {
                    acc[i][j] += av[i].x * wv[j].x;
                    acc[i][j] += av[i].y * wv[j].y;
                    acc[i][j] += av[i].z * wv[j].z;
                    acc[i][j] += av[i].w * wv[j].w;
                }
        }
        __syncthreads();
    }

    #pragma unroll
    for (int i = 0; i < 2; i++) {
        int b = b0 + bg + 32*i;
        #pragma unroll
        for (int j = 0; j < 4; j++) {
            int o = o0 + j;
            float v = acc[i][j] + b1[s*32 + o];
            buf_hidden[((size_t)b*32 + o)*100 + s] = fmaxf(v, 0.0f);
        }
    }
}

// ------------- Pass 3: out[b,j] = relu(sum_i hidden[b][i] * W2[j][i] + b2[j]) -------------
__global__ __launch_bounds__(128)
void final_kernel(const float* __restrict__ W2, const float* __restrict__ b2,
                  float* __restrict__ out) {
    const int b   = blockIdx.x;
    const int tid = threadIdx.x;
    float acc[6] = {0.f, 0.f, 0.f, 0.f, 0.f, 0.f};
    const float* xb = buf_hidden + (size_t)b * 3200;
    for (int i = tid; i < 3200; i += 128) {
        float v = xb[i];
        #pragma unroll
        for (int j = 0; j < 6; j++) acc[j] += v * W2[j*3200 + i];
    }
    #pragma unroll
    for (int off = 16; off > 0; off >>= 1)
        #pragma unroll
        for (int j = 0; j < 6; j++)
            acc[j] += __shfl_xor_sync(0xFFFFFFFFu, acc[j], off);
    __shared__ float red[4][6];
    if ((tid & 31) == 0) {
        #pragma unroll
        for (int j = 0; j < 6; j++) red[tid >> 5][j] = acc[j];
    }
    __syncthreads();
    if (tid < 6) {
        float t = red[0][tid] + red[1][tid] + red[2][tid] + red[3][tid] + b2[tid];
        out[b*6 + tid] = fmaxf(t, 0.0f);
    }
}

// ------------- entry point -------------
extern "C" void kernel_launch(void* const* d_in, const int* in_sizes, int n_in,
                              void* d_out, int out_size) {
    (void)in_sizes; (void)n_in; (void)out_size;
    const float* x  = (const float*)d_in[0];
    const float* W1 = (const float*)d_in[1];
    const float* b1 = (const float*)d_in[2];
    const float* W2 = (const float*)d_in[3];
    const float* b2 = (const float*)d_in[4];
    float* out = (float*)d_out;

    cudaFuncSetAttribute(fft_logabs_kernel, cudaFuncAttributeMaxDynamicSharedMemorySize, FFT_SMEM);
    cudaFuncSetAttribute(seg_gemm_kernel,   cudaFuncAttributeMaxDynamicSharedMemorySize, GEMM_SMEM);

    shim_two<<<1, 32>>>();                                      // idx 0
    shim_one<<<1, 32>>>();                                      // idx 1
    init_twiddles<<<25, 200>>>();                               // idx 2
    fft_logabs_kernel<<<NROWS, FFT_THREADS, FFT_SMEM>>>(x);     // idx 3 <- ncu window
    seg_gemm_kernel<<<400, 256, GEMM_SMEM>>>(W1, b1);           // idx 4
    final_kernel<<<256, 128>>>(W2, b2, out);                    // idx 5
}

// round 14
// speedup vs baseline: 1.7570x; 1.0295x over previous
#include <cuda_runtime.h>
#include <math.h>

// FFTConv pipeline, round 14 (retry of round-13 experiment; prior submission
// never ran due to broker container failure).
// FFT: 5 stages (4x radix-5 + merged radix-8), table-based untangle twiddles.
// GEMM: 800 blocks (segment x batch-eighth) for MLP on the mandatory DRAM stream.

#define NFFT 5000
#define NFULL 10000
#define NROWS (256*20)          // 5120 FFT rows
#define FFT_THREADS 512
#define FFT_SMEM (4*NFFT*4)     // 80000 B: re0, im0, re1, im1

#define PAD_A 108               // 108 mod 32 = 12 -> conflict-free float4 lane pattern
#define PAD_W 104
#define GEMM_ROWS 32            // batch rows per block (8 blocks per segment)
#define GEMM_SMEM ((GEMM_ROWS*PAD_A + 32*PAD_W)*4)   // 27136 B

// ------------- device-global scratch (heap allocation prohibited) -------------
__device__ float2 twid_s[NFFT];                  // exp(-2*pi*i*k/5000), stage table (40KB)
__device__ float2 twid_u[2501];                  // exp(-2*pi*i*k/10000), untangle table (20KB)
__device__ float  scr_logmag[(size_t)256*20*10000]; // log|FFT(x)|, [b][c][j]
__device__ float  scr_hidden[(size_t)256*32*100];   // relu(conv1), [b][o][s]
__device__ float  scr_sink;

// ------------- capture-window shims (ncu profiles in-call launch index 3) -------------
__global__ void pad_kernel_a() {
    if (threadIdx.x == 0) scr_sink = 7.0f;
}
__global__ void pad_kernel_b() {
    if (threadIdx.x == 0) scr_sink = 9.0f;
}

// ------------- twiddle-table initialization -------------
__global__ void setup_twiddles() {
    int k = blockIdx.x * blockDim.x + threadIdx.x;
    if (k < NFFT) {
        double ang = -2.0 * 3.14159265358979323846 * (double)k / (double)NFFT;
        twid_s[k] = make_float2((float)cos(ang), (float)sin(ang));
    }
    if (k < 2501) {
        double ang = -2.0 * 3.14159265358979323846 * (double)k / (double)NFULL;
        twid_u[k] = make_float2((float)cos(ang), (float)sin(ang));
    }
}

// ------------- complex multiply -------------
__device__ __forceinline__ float2 cxmul(float2 a, float2 b) {
    return make_float2(a.x*b.x - a.y*b.y, a.x*b.y + a.y*b.x);
}

// ------------- Stockham radix-5 stage -------------
template<int NS>
__device__ __forceinline__ void stage_r5(const float* __restrict__ ra, const float* __restrict__ ia,
                                         float* __restrict__ rb, float* __restrict__ ib, int tid) {
    const int STEP = NFFT / (NS * 5);
    for (int j = tid; j < NFFT/5; j += FFT_THREADS) {
        const int m = j % NS;
        const int t = m * STEP;
        float2 w1 = twid_s[t];
        float2 w2 = twid_s[2*t];
        float2 w3 = twid_s[3*t];
        float2 w4 = twid_s[4*t];
        float2 x0 = make_float2(ra[j],        ia[j]);
        float2 x1 = cxmul(make_float2(ra[j+1000], ia[j+1000]), w1);
        float2 x2 = cxmul(make_float2(ra[j+2000], ia[j+2000]), w2);
        float2 x3 = cxmul(make_float2(ra[j+3000], ia[j+3000]), w3);
        float2 x4 = cxmul(make_float2(ra[j+4000], ia[j+4000]), w4);
        float t1r = x1.x + x4.x, t1i = x1.y + x4.y;
        float t2r = x2.x + x3.x, t2i = x2.y + x3.y;
        float t3r = x1.x - x4.x, t3i = x1.y - x4.y;
        float t4r = x2.x - x3.x, t4i = x2.y - x3.y;
        const float c1 =  0.309016994374947424f;   // cos(2pi/5)
        const float c2 = -0.809016994374947424f;   // cos(4pi/5)
        const float s1 =  0.951056516295153572f;   // sin(2pi/5)
        const float s2 =  0.587785252292473129f;   // sin(4pi/5)
        float y0r = x0.x + t1r + t2r, y0i = x0.y + t1i + t2i;
        float par = x0.x + c1*t1r + c2*t2r, pai = x0.y + c1*t1i + c2*t2i;
        float pbr = s1*t3r + s2*t4r,        pbi = s1*t3i + s2*t4i;
        float pcr = x0.x + c2*t1r + c1*t2r, pci = x0.y + c2*t1i + c1*t2i;
        float pdr = s2*t3r - s1*t4r,        pdi = s2*t3i - s1*t4i;
        const int d = (j / NS) * (NS*5) + m;
        rb[d]        = y0r;       ib[d]        = y0i;
        rb[d +   NS] = par + pbi; ib[d +   NS] = pai - pbr;   // X1 = P - iQ
        rb[d + 2*NS] = pcr + pdi; ib[d + 2*NS] = pci - pdr;   // X2
        rb[d + 3*NS] = pcr - pdi; ib[d + 3*NS] = pci + pdr;   // X3
        rb[d + 4*NS] = par - pbi; ib[d + 4*NS] = pai + pbr;   // X4
    }
}

// ------------- merged Stockham radix-8 stage (NS=625, R=8, STEP=1) -------------
__device__ __forceinline__ void stage_r8(const float* __restrict__ ra, const float* __restrict__ ia,
                                         float* __restrict__ rb, float* __restrict__ ib, int tid) {
    for (int j = tid; j < 625; j += FFT_THREADS) {
        // twiddles exp(-2pi*i*j*r/5000) = twid_s[j*r]; max index 7*624 = 4368 < 5000
        float2 y0 = make_float2(ra[j],        ia[j]);
        float2 y1 = cxmul(make_float2(ra[j+ 625], ia[j+ 625]), twid_s[j]);
        float2 y2 = cxmul(make_float2(ra[j+1250], ia[j+1250]), twid_s[2*j]);
        float2 y3 = cxmul(make_float2(ra[j+1875], ia[j+1875]), twid_s[3*j]);
        float2 y4 = cxmul(make_float2(ra[j+2500], ia[j+2500]), twid_s[4*j]);
        float2 y5 = cxmul(make_float2(ra[j+3125], ia[j+3125]), twid_s[5*j]);
        float2 y6 = cxmul(make_float2(ra[j+3750], ia[j+3750]), twid_s[6*j]);
        float2 y7 = cxmul(make_float2(ra[j+4375], ia[j+4375]), twid_s[7*j]);
        // E = FFT4(y0,y2,y4,y6)
        float t0r=y0.x+y4.x, t0i=y0.y+y4.y;
        float t1r=y0.x-y4.x, t1i=y0.y-y4.y;
        float t2r=y2.x+y6.x, t2i=y2.y+y6.y;
        float t3r=y2.x-y6.x, t3i=y2.y-y6.y;
        float E0r=t0r+t2r, E0i=t0i+t2i;
        float E1r=t1r+t3i, E1i=t1i-t3r;
        float E2r=t0r-t2r, E2i=t0i-t2i;
        float E3r=t1r-t3i, E3i=t1i+t3r;
        // O = FFT4(y1,y3,y5,y7)
        float u0r=y1.x+y5.x, u0i=y1.y+y5.y;
        float u1r=y1.x-y5.x, u1i=y1.y-y5.y;
        float u2r=y3.x+y7.x, u2i=y3.y+y7.y;
        float u3r=y3.x-y7.x, u3i=y3.y-y7.y;
        float O0r=u0r+u2r, O0i=u0i+u2i;
        float O1r=u1r+u3i, O1i=u1i-u3r;
        float O2r=u0r-u2r, O2i=u0i-u2i;
        float O3r=u1r-u3i, O3i=u1i+u3r;
        const float RT2 = 0.70710678118654752440f;      // sqrt(2)/2
        float a1r = RT2*(O1r+O1i), a1i = RT2*(O1i-O1r); // W8^1 * O1
        float a2r = O2i,           a2i = -O2r;          // W8^2 * O2 = -i*O2
        float a3r = RT2*(O3i-O3r), a3i = -RT2*(O3r+O3i);// W8^3 * O3
        rb[j]      = E0r+O0r; ib[j]      = E0i+O0i;
        rb[j+ 625] = E1r+a1r; ib[j+ 625] = E1i+a1i;
        rb[j+1250] = E2r+a2r; ib[j+1250] = E2i+a2i;
        rb[j+1875] = E3r+a3r; ib[j+1875] = E3i+a3i;
        rb[j+2500] = E0r-O0r; ib[j+2500] = E0i-O0i;
        rb[j+3125] = E1r-a1r; ib[j+3125] = E1i-a1i;
        rb[j+3750] = E2r-a2r; ib[j+3750] = E2i-a2i;
        rb[j+4375] = E3r-a3r; ib[j+4375] = E3i-a3i;
    }
}

// ------------- Pass 1: real FFT of length 10000 (packed 5000-point) + log|.| -------------
__global__ __launch_bounds__(FFT_THREADS, 2)
void fft_logabs_kernel(const float* __restrict__ x) {
    extern __shared__ float sm[];
    float* re0 = sm;
    float* im0 = sm + NFFT;
    float* re1 = sm + 2*NFFT;
    float* im1 = sm + 3*NFFT;
    const int tid = threadIdx.x;
    const size_t row = blockIdx.x;

    // pack: z[n] = x[2n] + i*x[2n+1]
    const float2* xin = (const float2*)(x + row * NFULL);
    for (int n = tid; n < NFFT; n += FFT_THREADS) {
        float2 v = xin[n];
        re0[n] = v.x; im0[n] = v.y;
    }
    __syncthreads();

    stage_r5<1>  (re0, im0, re1, im1, tid); __syncthreads();
    stage_r5<5>  (re1, im1, re0, im0, tid); __syncthreads();
    stage_r5<25> (re0, im0, re1, im1, tid); __syncthreads();
    stage_r5<125>(re1, im1, re0, im0, tid); __syncthreads();
    stage_r8     (re0, im0, re1, im1, tid); __syncthreads();
    // Z[k] resident in (re1, im1)

    float* outp = scr_logmag + row * NFULL;
    for (int k = tid; k <= 2500; k += FFT_THREADS) {
        const int km = (k == 0) ? 0 : (NFFT - k);
        float ar = re1[k],  ai = im1[k];
        float br = re1[km], bi = im1[km];
        // untangle: E = (Z[k] + conj(Z[-k]))/2 ; O = (Z[k] - conj(Z[-k]))/(2i)
        float Er = 0.5f*(ar + br), Ei = 0.5f*(ai - bi);
        float Or = 0.5f*(ai + bi), Oi = 0.5f*(br - ar);
        float2 w = twid_u[k];            // exp(-2*pi*i*k/10000)
        float tr = w.x*Or - w.y*Oi;
        float ti = w.x*Oi + w.y*Or;
        float pr = Er + tr, pi = Ei + ti;   // X[k]
        float mr = Er - tr, mi = Ei - ti;   // X[5000+k]; |X[5000+k]| == |X[5000-k]|
        float l1 = 0.5f * logf(pr*pr + pi*pi);
        float l2 = 0.5f * logf(mr*mr + mi*mi);
        outp[k]        = l1;
        outp[5000 - k] = l2;
        if (k > 0) {
            outp[10000 - k] = l1;   // real-input conjugate symmetry
            outp[5000 + k]  = l2;
        }
    }
}

// ------------- Pass 2: per-segment GEMM, batch split 8 ways -------------
// hidden[b,o,s] = relu( sum_{c,k} logmag[b,c,s*100+k] * W1[s,o,c,k] + b1[s,o] )
// Grid 800 = segment x batch-eighth. 256 threads; 32 b-rows (one per lane); all 32 o.
__global__ __launch_bounds__(256)
void seg_gemm_kernel(const float* __restrict__ W1, const float* __restrict__ b1) {
    extern __shared__ float sm[];
    float* Asm = sm;                        // [32][PAD_A] (100 valid k)
    float* Wsm = sm + GEMM_ROWS * PAD_A;    // [32][PAD_W]
    const int s    = blockIdx.x >> 3;
    const int b0   = (blockIdx.x & 7) * GEMM_ROWS;
    const int tid  = threadIdx.x;
    const int lane = tid & 31;              // local batch row
    const int og   = tid >> 5;              // warp -> output-channel group
    const int o0   = og * 4;

    float acc[4] = {0.f, 0.f, 0.f, 0.f};

    for (int c = 0; c < 20; c++) {
        // A tile: 32 rows x 100 floats (float4, coalesced)
        for (int q = tid; q < GEMM_ROWS*25; q += 256) {
            int b  = q / 25;
            int kq = q % 25;
            float4 v = *(const float4*)(scr_logmag + ((size_t)(b0 + b)*20 + c)*10000 + s*100 + kq*4);
            *(float4*)(Asm + b*PAD_A + kq*4) = v;
        }
        // W tile: 32 rows x 100 floats
        for (int q = tid; q < 800; q += 256) {
            int o  = q / 25;
            int kq = q % 25;
            float4 v = *(const float4*)(W1 + (((size_t)s*32 + o)*20 + c)*100 + kq*4);
            *(float4*)(Wsm + o*PAD_W + kq*4) = v;
        }
        __syncthreads();

        for (int k = 0; k < 100; k += 4) {
            float4 wv[4];
            #pragma unroll
            for (int j = 0; j < 4; j++)     // warp-uniform address -> broadcast read
                wv[j] = *(const float4*)(Wsm + (o0 + j)*PAD_W + k);
            float4 av = *(const float4*)(Asm + lane*PAD_A + k);
            #pragma unroll
            for (int j = 0; j < 4; j++) {
                acc[j] += av.x * wv[j].x;
                acc[j] += av.y * wv[j].y;
                acc[j] += av.z * wv[j].z;
                acc[j] += av.w * wv[j].w;
            }
        }
        __syncthreads();
    }

    const int b = b0 + lane;
    #pragma unroll
    for (int j = 0; j < 4; j++) {
        int o = o0 + j;
        float v = acc[j] + b1[s*32 + o];
        scr_hidden[((size_t)b*32 + o)*100 + s] = fmaxf(v, 0.0f);
    }
}

// ------------- Pass 3: out[b,j] = relu(sum_i hidden[b][i] * W2[j][i] + b2[j]) -------------
__global__ __launch_bounds__(128)
void final_kernel(const float* __restrict__ W2, const float* __restrict__ b2,
                  float* __restrict__ out) {
    const int b   = blockIdx.x;
    const int tid = threadIdx.x;
    float acc[6] = {0.f, 0.f, 0.f, 0.f, 0.f, 0.f};
    const float* xb = scr_hidden + (size_t)b * 3200;
    for (int i = tid; i < 3200; i += 128) {
        float v = xb[i];
        #pragma unroll
        for (int j = 0; j < 6; j++) acc[j] += v * W2[j*3200 + i];
    }
    #pragma unroll
    for (int off = 16; off > 0; off >>= 1)
        #pragma unroll
        for (int j = 0; j < 6; j++)
            acc[j] += __shfl_xor_sync(0xFFFFFFFFu, acc[j], off);
    __shared__ float red[4][6];
    if ((tid & 31) == 0) {
        #pragma unroll
        for (int j = 0; j < 6; j++) red[tid >> 5][j] = acc[j];
    }
    __syncthreads();
    if (tid < 6) {
        float t = red[0][tid] + red[1][tid] + red[2][tid] + red[3][tid] + b2[tid];
        out[b*6 + tid] = fmaxf(t, 0.0f);
    }
}

// ------------- entry point -------------
extern "C" void kernel_launch(void* const* d_in, const int* in_sizes, int n_in,
                              void* d_out, int out_size) {
    (void)in_sizes; (void)n_in; (void)out_size;
    const float* x  = (const float*)d_in[0];
    const float* W1 = (const float*)d_in[1];
    const float* b1 = (const float*)d_in[2];
    const float* W2 = (const float*)d_in[3];
    const float* b2 = (const float*)d_in[4];
    float* out = (float*)d_out;

    cudaFuncSetAttribute(fft_logabs_kernel, cudaFuncAttributeMaxDynamicSharedMemorySize, FFT_SMEM);
    cudaFuncSetAttribute(seg_gemm_kernel,   cudaFuncAttributeMaxDynamicSharedMemorySize, GEMM_SMEM);

    pad_kernel_b<<<1, 32>>>();                                  // idx 0
    pad_kernel_a<<<1, 32>>>();                                  // idx 1
    setup_twiddles<<<20, 256>>>();                              // idx 2
    fft_logabs_kernel<<<NROWS, FFT_THREADS, FFT_SMEM>>>(x);     // idx 3 <- ncu window
    seg_gemm_kernel<<<800, 256, GEMM_SMEM>>>(W1, b1);           // idx 4
    final_kernel<<<256, 128>>>(W2, b2, out);                    // idx 5
}

// round 15
// speedup vs baseline: 2.1226x; 1.2081x over previous
#include <cuda_runtime.h>
#include <math.h>

// FFTConv pipeline, round 15.
// FFT twiddle overhaul: (a) item remap so warp-mates share the twiddle index
// (broadcast LDG instead of 16-32 line gathers), (b) w^2..w^7 computed from w^1
// by complex multiplication (FMA pipe has headroom; L1tex does not).

#define NFFT 5000
#define NFULL 10000
#define NROWS (256*20)          // 5120 FFT rows
#define FFT_THREADS 512
#define FFT_SMEM (4*NFFT*4)     // 80000 B: re0, im0, re1, im1

#define PAD_A 108               // 108 mod 32 = 12 -> conflict-free float4 lane pattern
#define PAD_W 104
#define GEMM_ROWS 32            // batch rows per block (8 blocks per segment)
#define GEMM_SMEM ((GEMM_ROWS*PAD_A + 32*PAD_W)*4)   // 27136 B

// ------------- device-global scratch (heap allocation prohibited) -------------
__device__ float2 twid_s[NFFT];                  // exp(-2*pi*i*k/5000), stage table
__device__ float2 twid_u[2501];                  // exp(-2*pi*i*k/10000), untangle table
__device__ float  scr_logmag[(size_t)256*20*10000]; // log|FFT(x)|, [b][c][j]
__device__ float  scr_hidden[(size_t)256*32*100];   // relu(conv1), [b][o][s]
__device__ float  scr_sink;

// ------------- capture-window shims (ncu profiles in-call launch index 3) -------------
__global__ void pad_kernel_a() {
    if (threadIdx.x == 0) scr_sink = 7.0f;
}
__global__ void pad_kernel_b() {
    if (threadIdx.x == 0) scr_sink = 9.0f;
}

// ------------- twiddle-table initialization -------------
__global__ void setup_twiddles() {
    int k = blockIdx.x * blockDim.x + threadIdx.x;
    if (k < NFFT) {
        double ang = -2.0 * 3.14159265358979323846 * (double)k / (double)NFFT;
        twid_s[k] = make_float2((float)cos(ang), (float)sin(ang));
    }
    if (k < 2501) {
        double ang = -2.0 * 3.14159265358979323846 * (double)k / (double)NFULL;
        twid_u[k] = make_float2((float)cos(ang), (float)sin(ang));
    }
}

// ------------- complex multiply -------------
__device__ __forceinline__ float2 cxmul(float2 a, float2 b) {
    return make_float2(a.x*b.x - a.y*b.y, a.x*b.y + a.y*b.x);
}

// ------------- Stockham radix-5 stage, twiddle-broadcast item order -------------
// Items i in [0,1000) enumerated as q = i % Q, m = i / Q (Q = 1000/NS), j = m + NS*q.
// Warp-mates share m -> twid_s[m*STEP] is a broadcast; only w^1 is loaded,
// w^2..w^4 computed. LDS strides NS (read) and 5*NS (write) are coprime to 32.
template<int NS>
__device__ __forceinline__ void stage_r5(const float* __restrict__ ra, const float* __restrict__ ia,
                                         float* __restrict__ rb, float* __restrict__ ib, int tid) {
    const int STEP = NFFT / (NS * 5);
    const int Q = 1000 / NS;
    for (int i = tid; i < 1000; i += FFT_THREADS) {
        const int q = i % Q;
        const int m = i / Q;
        const int j = m + NS * q;
        float2 w1 = twid_s[m * STEP];
        float2 w2 = cxmul(w1, w1);
        float2 w3 = cxmul(w2, w1);
        float2 w4 = cxmul(w2, w2);
        float2 x0 = make_float2(ra[j],        ia[j]);
        float2 x1 = cxmul(make_float2(ra[j+1000], ia[j+1000]), w1);
        float2 x2 = cxmul(make_float2(ra[j+2000], ia[j+2000]), w2);
        float2 x3 = cxmul(make_float2(ra[j+3000], ia[j+3000]), w3);
        float2 x4 = cxmul(make_float2(ra[j+4000], ia[j+4000]), w4);
        float t1r = x1.x + x4.x, t1i = x1.y + x4.y;
        float t2r = x2.x + x3.x, t2i = x2.y + x3.y;
        float t3r = x1.x - x4.x, t3i = x1.y - x4.y;
        float t4r = x2.x - x3.x, t4i = x2.y - x3.y;
        const float c1 =  0.309016994374947424f;   // cos(2pi/5)
        const float c2 = -0.809016994374947424f;   // cos(4pi/5)
        const float s1 =  0.951056516295153572f;   // sin(2pi/5)
        const float s2 =  0.587785252292473129f;   // sin(4pi/5)
        float y0r = x0.x + t1r + t2r, y0i = x0.y + t1i + t2i;
        float par = x0.x + c1*t1r + c2*t2r, pai = x0.y + c1*t1i + c2*t2i;
        float pbr = s1*t3r + s2*t4r,        pbi = s1*t3i + s2*t4i;
        float pcr = x0.x + c2*t1r + c1*t2r, pci = x0.y + c2*t1i + c1*t2i;
        float pdr = s2*t3r - s1*t4r,        pdi = s2*t3i - s1*t4i;
        const int d = q * (NS * 5) + m;
        rb[d]        = y0r;       ib[d]        = y0i;
        rb[d +   NS] = par + pbi; ib[d +   NS] = pai - pbr;   // X1 = P - iQ
        rb[d + 2*NS] = pcr + pdi; ib[d + 2*NS] = pci - pdr;   // X2
        rb[d + 3*NS] = pcr - pdi; ib[d + 3*NS] = pci + pdr;   // X3
        rb[d + 4*NS] = par - pbi; ib[d + 4*NS] = pai + pbr;   // X4
    }
}

// ------------- merged Stockham radix-8 stage (NS=625): one coalesced twiddle load -------------
__device__ __forceinline__ void stage_r8(const float* __restrict__ ra, const float* __restrict__ ia,
                                         float* __restrict__ rb, float* __restrict__ ib, int tid) {
    for (int j = tid; j < 625; j += FFT_THREADS) {
        float2 w1 = twid_s[j];           // stride-1 coalesced; exp(-2pi*i*j/5000)
        float2 w2 = cxmul(w1, w1);
        float2 w3 = cxmul(w2, w1);
        float2 w4 = cxmul(w2, w2);
        float2 w5 = cxmul(w4, w1);
        float2 w6 = cxmul(w4, w2);
        float2 w7 = cxmul(w4, w3);
        float2 y0 = make_float2(ra[j],        ia[j]);
        float2 y1 = cxmul(make_float2(ra[j+ 625], ia[j+ 625]), w1);
        float2 y2 = cxmul(make_float2(ra[j+1250], ia[j+1250]), w2);
        float2 y3 = cxmul(make_float2(ra[j+1875], ia[j+1875]), w3);
        float2 y4 = cxmul(make_float2(ra[j+2500], ia[j+2500]), w4);
        float2 y5 = cxmul(make_float2(ra[j+3125], ia[j+3125]), w5);
        float2 y6 = cxmul(make_float2(ra[j+3750], ia[j+3750]), w6);
        float2 y7 = cxmul(make_float2(ra[j+4375], ia[j+4375]), w7);
        // E = FFT4(y0,y2,y4,y6)
        float t0r=y0.x+y4.x, t0i=y0.y+y4.y;
        float t1r=y0.x-y4.x, t1i=y0.y-y4.y;
        float t2r=y2.x+y6.x, t2i=y2.y+y6.y;
        float t3r=y2.x-y6.x, t3i=y2.y-y6.y;
        float E0r=t0r+t2r, E0i=t0i+t2i;
        float E1r=t1r+t3i, E1i=t1i-t3r;
        float E2r=t0r-t2r, E2i=t0i-t2i;
        float E3r=t1r-t3i, E3i=t1i+t3r;
        // O = FFT4(y1,y3,y5,y7)
        float u0r=y1.x+y5.x, u0i=y1.y+y5.y;
        float u1r=y1.x-y5.x, u1i=y1.y-y5.y;
        float u2r=y3.x+y7.x, u2i=y3.y+y7.y;
        float u3r=y3.x-y7.x, u3i=y3.y-y7.y;
        float O0r=u0r+u2r, O0i=u0i+u2i;
        float O1r=u1r+u3i, O1i=u1i-u3r;
        float O2r=u0r-u2r, O2i=u0i-u2i;
        float O3r=u1r-u3i, O3i=u1i+u3r;
        const float RT2 = 0.70710678118654752440f;      // sqrt(2)/2
        float a1r = RT2*(O1r+O1i), a1i = RT2*(O1i-O1r); // W8^1 * O1
        float a2r = O2i,           a2i = -O2r;          // W8^2 * O2 = -i*O2
        float a3r = RT2*(O3i-O3r), a3i = -RT2*(O3r+O3i);// W8^3 * O3
        rb[j]      = E0r+O0r; ib[j]      = E0i+O0i;
        rb[j+ 625] = E1r+a1r; ib[j+ 625] = E1i+a1i;
        rb[j+1250] = E2r+a2r; ib[j+1250] = E2i+a2i;
        rb[j+1875] = E3r+a3r; ib[j+1875] = E3i+a3i;
        rb[j+2500] = E0r-O0r; ib[j+2500] = E0i-O0i;
        rb[j+3125] = E1r-a1r; ib[j+3125] = E1i-a1i;
        rb[j+3750] = E2r-a2r; ib[j+3750] = E2i-a2i;
        rb[j+4375] = E3r-a3r; ib[j+4375] = E3i-a3i;
    }
}

// ------------- Pass 1: real FFT of length 10000 (packed 5000-point) + log|.| -------------
__global__ __launch_bounds__(FFT_THREADS, 2)
void fft_logabs_kernel(const float* __restrict__ x) {
    extern __shared__ float sm[];
    float* re0 = sm;
    float* im0 = sm + NFFT;
    float* re1 = sm + 2*NFFT;
    float* im1 = sm + 3*NFFT;
    const int tid = threadIdx.x;
    const size_t row = blockIdx.x;

    // pack: z[n] = x[2n] + i*x[2n+1]
    const float2* xin = (const float2*)(x + row * NFULL);
    for (int n = tid; n < NFFT; n += FFT_THREADS) {
        float2 v = xin[n];
        re0[n] = v.x; im0[n] = v.y;
    }
    __syncthreads();

    stage_r5<1>  (re0, im0, re1, im1, tid); __syncthreads();
    stage_r5<5>  (re1, im1, re0, im0, tid); __syncthreads();
    stage_r5<25> (re0, im0, re1, im1, tid); __syncthreads();
    stage_r5<125>(re1, im1, re0, im0, tid); __syncthreads();
    stage_r8     (re0, im0, re1, im1, tid); __syncthreads();
    // Z[k] resident in (re1, im1)

    float* outp = scr_logmag + row * NFULL;
    for (int k = tid; k <= 2500; k += FFT_THREADS) {
        const int km = (k == 0) ? 0 : (NFFT - k);
        float ar = re1[k],  ai = im1[k];
        float br = re1[km], bi = im1[km];
        // untangle: E = (Z[k] + conj(Z[-k]))/2 ; O = (Z[k] - conj(Z[-k]))/(2i)
        float Er = 0.5f*(ar + br), Ei = 0.5f*(ai - bi);
        float Or = 0.5f*(ai + bi), Oi = 0.5f*(br - ar);
        float2 w = twid_u[k];            // exp(-2*pi*i*k/10000), stride-1 coalesced
        float tr = w.x*Or - w.y*Oi;
        float ti = w.x*Oi + w.y*Or;
        float pr = Er + tr, pi = Ei + ti;   // X[k]
        float mr = Er - tr, mi = Ei - ti;   // X[5000+k]; |X[5000+k]| == |X[5000-k]|
        float l1 = 0.5f * logf(pr*pr + pi*pi);
        float l2 = 0.5f * logf(mr*mr + mi*mi);
        outp[k]        = l1;
        outp[5000 - k] = l2;
        if (k > 0) {
            outp[10000 - k] = l1;   // real-input conjugate symmetry
            outp[5000 + k]  = l2;
        }
    }
}

// ------------- Pass 2: per-segment GEMM, batch split 8 ways (unchanged) -------------
// hidden[b,o,s] = relu( sum_{c,k} logmag[b,c,s*100+k] * W1[s,o,c,k] + b1[s,o] )
__global__ __launch_bounds__(256)
void seg_gemm_kernel(const float* __restrict__ W1, const float* __restrict__ b1) {
    extern __shared__ float sm[];
    float* Asm = sm;                        // [32][PAD_A] (100 valid k)
    float* Wsm = sm + GEMM_ROWS * PAD_A;    // [32][PAD_W]
    const int s    = blockIdx.x >> 3;
    const int b0   = (blockIdx.x & 7) * GEMM_ROWS;
    const int tid  = threadIdx.x;
    const int lane = tid & 31;              // local batch row
    const int og   = tid >> 5;              // warp -> output-channel group
    const int o0   = og * 4;

    float acc[4] = {0.f, 0.f, 0.f, 0.f};

    for (int c = 0; c < 20; c++) {
        for (int q = tid; q < GEMM_ROWS*25; q += 256) {
            int b  = q / 25;
            int kq = q % 25;
            float4 v = *(const float4*)(scr_logmag + ((size_t)(b0 + b)*20 + c)*10000 + s*100 + kq*4);
            *(float4*)(Asm + b*PAD_A + kq*4) = v;
        }
        for (int q = tid; q < 800; q += 256) {
            int o  = q / 25;
            int kq = q % 25;
            float4 v = *(const float4*)(W1 + (((size_t)s*32 + o)*20 + c)*100 + kq*4);
            *(float4*)(Wsm + o*PAD_W + kq*4) = v;
        }
        __syncthreads();

        for (int k = 0; k < 100; k += 4) {
            float4 wv[4];
            #pragma unroll
            for (int j = 0; j < 4; j++)     // warp-uniform address -> broadcast read
                wv[j] = *(const float4*)(Wsm + (o0 + j)*PAD_W + k);
            float4 av = *(const float4*)(Asm + lane*PAD_A + k);
            #pragma unroll
            for (int j = 0; j < 4; j++) {
                acc[j] += av.x * wv[j].x;
                acc[j] += av.y * wv[j].y;
                acc[j] += av.z * wv[j].z;
                acc[j] += av.w * wv[j].w;
            }
        }
        __syncthreads();
    }

    const int b = b0 + lane;
    #pragma unroll
    for (int j = 0; j < 4; j++) {
        int o = o0 + j;
        float v = acc[j] + b1[s*32 + o];
        scr_hidden[((size_t)b*32 + o)*100 + s] = fmaxf(v, 0.0f);
    }
}

// ------------- Pass 3: out[b,j] = relu(sum_i hidden[b][i] * W2[j][i] + b2[j]) -------------
__global__ __launch_bounds__(128)
void final_kernel(const float* __restrict__ W2, const float* __restrict__ b2,
                  float* __restrict__ out) {
    const int b   = blockIdx.x;
    const int tid = threadIdx.x;
    float acc[6] = {0.f, 0.f, 0.f, 0.f, 0.f, 0.f};
    const float* xb = scr_hidden + (size_t)b * 3200;
    for (int i = tid; i < 3200; i += 128) {
        float v = xb[i];
        #pragma unroll
        for (int j = 0; j < 6; j++) acc[j] += v * W2[j*3200 + i];
    }
    #pragma unroll
    for (int off = 16; off > 0; off >>= 1)
        #pragma unroll
        for (int j = 0; j < 6; j++)
            acc[j] += __shfl_xor_sync(0xFFFFFFFFu, acc[j], off);
    __shared__ float red[4][6];
    if ((tid & 31) == 0) {
        #pragma unroll
        for (int j = 0; j < 6; j++) red[tid >> 5][j] = acc[j];
    }
    __syncthreads();
    if (tid < 6) {
        float t = red[0][tid] + red[1][tid] + red[2][tid] + red[3][tid] + b2[tid];
        out[b*6 + tid] = fmaxf(t, 0.0f);
    }
}

// ------------- entry point -------------
extern "C" void kernel_launch(void* const* d_in, const int* in_sizes, int n_in,
                              void* d_out, int out_size) {
    (void)in_sizes; (void)n_in; (void)out_size;
    const float* x  = (const float*)d_in[0];
    const float* W1 = (const float*)d_in[1];
    const float* b1 = (const float*)d_in[2];
    const float* W2 = (const float*)d_in[3];
    const float* b2 = (const float*)d_in[4];
    float* out = (float*)d_out;

    cudaFuncSetAttribute(fft_logabs_kernel, cudaFuncAttributeMaxDynamicSharedMemorySize, FFT_SMEM);
    cudaFuncSetAttribute(seg_gemm_kernel,   cudaFuncAttributeMaxDynamicSharedMemorySize, GEMM_SMEM);

    pad_kernel_b<<<1, 32>>>();                                  // idx 0
    pad_kernel_a<<<1, 32>>>();                                  // idx 1
    setup_twiddles<<<20, 256>>>();                              // idx 2
    fft_logabs_kernel<<<NROWS, FFT_THREADS, FFT_SMEM>>>(x);     // idx 3 <- ncu window
    seg_gemm_kernel<<<800, 256, GEMM_SMEM>>>(W1, b1);           // idx 4
    final_kernel<<<256, 128>>>(W2, b2, out);                    // idx 5
}